// round 4
// baseline (speedup 1.0000x reference)
#include <cuda_runtime.h>

// ---------------------------------------------------------------------------
// TFN interaction block, fully fused fp32 implementation.
//
//  Kernel 1: zero node accumulators (g_agg).
//  Kernel 2: per-edge. CTA = 256 thr = 8 warps, processes 16 edges.
//            Each warp owns 2 edges; tpw (1024 weights/edge) lives in
//            registers (32/lane/edge), w2 streamed through smem in
//            8x1024 chunks. Epilogue contracts tpw against the edge
//            feature coefficients and atomically scatters msg into g_agg.
//  Kernel 3: per-node linear (lin_w0 / lin_w1) + gated SiLU + residual.
// ---------------------------------------------------------------------------

#define NMAX 10000

__device__ float g_agg[NMAX * 64];   // [n][0:16] = agg_s[u], [n][16+u*3+i] = agg_v[u][i]

// --------------------------------------------------------------------------
__global__ void zero_kernel(int n4)
{
    int i = blockIdx.x * blockDim.x + threadIdx.x;
    if (i < n4) reinterpret_cast<float4*>(g_agg)[i] = make_float4(0.f, 0.f, 0.f, 0.f);
}

// --------------------------------------------------------------------------
// Epilogue: contract tpw (register array A, A[g*8+uh] holds tpw[g, u=uh*2+ul, v=lane&15])
// against per-edge coefficients, reduce over u-parity (shfl_xor 16), scatter.
__device__ __forceinline__ void contract_and_scatter(
    const float (&A)[32], const float* sf, const float* ss,
    int dst, bool act, int lane)
{
    const int   v  = lane & 15;
    const int   ul = lane >> 4;
    const float shs = ss[0], sv0 = ss[1], sv1 = ss[2], sv2 = ss[3];
    const float inv_sqrt3 = 0.57735026919f;

    float ps = 0.f, t1 = 0.f, t20 = 0.f, t21 = 0.f, t22 = 0.f;
#pragma unroll
    for (int uh = 0; uh < 8; uh++) {
        int   u  = uh * 2 + ul;
        float xs = sf[u];
        float x0 = sf[16 + u * 3 + 0];
        float x1 = sf[16 + u * 3 + 1];
        float x2 = sf[16 + u * 3 + 2];
        float av = xs * shs;                                      // a_u
        float bv = inv_sqrt3 * (x0 * sv0 + x1 * sv1 + x2 * sv2);  // b_u
        ps += av * A[uh]        + bv * A[24 + uh];  // W00, W11
        t1 += xs * A[8 + uh];                       // W01
        float w10 = A[16 + uh];                     // W10
        t20 += (x0 * shs) * w10;
        t21 += (x1 * shs) * w10;
        t22 += (x2 * shs) * w10;
    }
    // reduce over the two u-parities (lanes ^16)
    ps  += __shfl_xor_sync(0xffffffffu, ps, 16);
    t1  += __shfl_xor_sync(0xffffffffu, t1, 16);
    t20 += __shfl_xor_sync(0xffffffffu, t20, 16);
    t21 += __shfl_xor_sync(0xffffffffu, t21, 16);
    t22 += __shfl_xor_sync(0xffffffffu, t22, 16);

    if (act && ul == 0) {
        const float alpha = 0.17677669529f;  // 1/sqrt(2*MUL)
        float* dp = g_agg + (long long)dst * 64;
        atomicAdd(dp + v,                alpha * ps);
        atomicAdd(dp + 16 + v * 3 + 0,   alpha * (t1 * sv0 + t20));
        atomicAdd(dp + 16 + v * 3 + 1,   alpha * (t1 * sv1 + t21));
        atomicAdd(dp + 16 + v * 3 + 2,   alpha * (t1 * sv2 + t22));
    }
}

// --------------------------------------------------------------------------
__global__ __launch_bounds__(256, 2)
void edge_kernel(const float* __restrict__ nf,  const float* __restrict__ esh,
                 const float* __restrict__ emb, const float* __restrict__ w1,
                 const float* __restrict__ b1,  const float* __restrict__ w2,
                 const float* __restrict__ b2,  const int*   __restrict__ eidx,
                 int E)
{
    __shared__ float s_w2[8 * 1024];   // 32 KB: one k-chunk of w2, natural [k][j]
    __shared__ float s_h[16 * 64];     // h per edge
    __shared__ float s_w1[16 * 64];    // staged w1
    __shared__ float s_feat[16 * 64];  // raw gathered node features per edge
    __shared__ float s_sh[16 * 4];     // edge_sh per edge

    const int tid  = threadIdx.x;
    const int wid  = tid >> 5;
    const int lane = tid & 31;

    // stage w1 (1024 floats == 256 float4, one per thread)
    reinterpret_cast<float4*>(s_w1)[tid] = reinterpret_cast<const float4*>(w1)[tid];
    __syncthreads();

    const long long base = (long long)blockIdx.x * 16;
    int  dsts[2];
    bool act[2];

#pragma unroll
    for (int r = 0; r < 2; r++) {
        const int eL = wid * 2 + r;
        long long e  = base + eL;
        bool a       = (e < E);
        long long ec = a ? e : 0;
        act[r]  = a;
        int src = eidx[ec];
        dsts[r] = eidx[E + ec];

        // h = silu(emb @ w1 + b1)
        float embv = (lane < 16) ? emb[ec * 16 + lane] : 0.f;
        float h0 = b1[lane], h1 = b1[lane + 32];
#pragma unroll
        for (int nb = 0; nb < 16; nb++) {
            float ev = __shfl_sync(0xffffffffu, embv, nb);
            h0 += ev * s_w1[nb * 64 + lane];
            h1 += ev * s_w1[nb * 64 + lane + 32];
        }
        s_h[eL * 64 + lane]      = h0 / (1.f + expf(-h0));
        s_h[eL * 64 + lane + 32] = h1 / (1.f + expf(-h1));

        const float* nfp = nf + (long long)src * 64;
        s_feat[eL * 64 + lane]      = nfp[lane];
        s_feat[eL * 64 + lane + 32] = nfp[lane + 32];
        if (lane < 4) s_sh[eL * 4 + lane] = esh[ec * 4 + lane];
    }

    // tpw accumulators, init with bias b2.  A[g*8+uh] <-> j = g*256 + uh*32 + lane
    float a0[32], a1[32];
#pragma unroll
    for (int r = 0; r < 32; r++) {
        float bb = b2[(r >> 3) * 256 + (r & 7) * 32 + lane];
        a0[r] = bb;
        a1[r] = bb;
    }

    const int eL0 = wid * 2, eL1 = wid * 2 + 1;

    for (int kc = 0; kc < 8; kc++) {
        __syncthreads();
        {   // cooperative load of w2 rows [kc*8, kc*8+8) -> smem (coalesced float4)
            const int kr = tid >> 5;
            const float4* s4 = reinterpret_cast<const float4*>(w2 + (kc * 8 + kr) * 1024);
            float4*       d4 = reinterpret_cast<float4*>(s_w2 + kr * 1024);
#pragma unroll
            for (int it = 0; it < 8; it++) d4[lane + it * 32] = s4[lane + it * 32];
        }
        __syncthreads();

#pragma unroll
        for (int k8 = 0; k8 < 8; k8++) {
            float h0 = s_h[eL0 * 64 + kc * 8 + k8];   // LDS broadcast
            float h1 = s_h[eL1 * 64 + kc * 8 + k8];
            const float* wrow = s_w2 + k8 * 1024 + lane;
#pragma unroll
            for (int r = 0; r < 32; r++) {
                float w = wrow[(r >> 3) * 256 + (r & 7) * 32];  // conflict-free: stride 4B across lanes
                a0[r] += h0 * w;
                a1[r] += h1 * w;
            }
        }
    }
    __syncwarp();

    contract_and_scatter(a0, s_feat + eL0 * 64, s_sh + eL0 * 4, dsts[0], act[0], lane);
    contract_and_scatter(a1, s_feat + eL1 * 64, s_sh + eL1 * 4, dsts[1], act[1], lane);
}

// --------------------------------------------------------------------------
__global__ void node_kernel(const float* __restrict__ nf,
                            const float* __restrict__ lw0,
                            const float* __restrict__ lw1,
                            float* __restrict__ out, int N)
{
    int idx = blockIdx.x * blockDim.x + threadIdx.x;
    int n = idx >> 4, v = idx & 15;
    if (n >= N) return;

    const float* ag = g_agg + (long long)n * 64;
    float ts = 0.f, tv0 = 0.f, tv1 = 0.f, tv2 = 0.f;
#pragma unroll
    for (int u = 0; u < 16; u++) {
        float l0 = __ldg(lw0 + u * 16 + v);
        float l1 = __ldg(lw1 + u * 16 + v);
        ts  += ag[u] * l0;
        tv0 += ag[16 + u * 3 + 0] * l1;
        tv1 += ag[16 + u * 3 + 1] * l1;
        tv2 += ag[16 + u * 3 + 2] * l1;
    }
    const float s = 0.25f;            // 1/sqrt(MUL)
    ts *= s; tv0 *= s; tv1 *= s; tv2 *= s;

    const float eps = 1e-8f;
    float ns = fabsf(ts);
    float gs = ns / ((1.f + expf(-ns)) * (ns + eps));   // silu(ns)/(ns+eps)
    float nv = sqrtf(tv0 * tv0 + tv1 * tv1 + tv2 * tv2);
    float gv = nv / ((1.f + expf(-nv)) * (nv + eps));

    const float* nfp = nf + (long long)n * 64;
    float*       op  = out + (long long)n * 64;
    op[v]                = nfp[v]                + ts  * gs;
    op[16 + v * 3 + 0]   = nfp[16 + v * 3 + 0]   + tv0 * gv;
    op[16 + v * 3 + 1]   = nfp[16 + v * 3 + 1]   + tv1 * gv;
    op[16 + v * 3 + 2]   = nfp[16 + v * 3 + 2]   + tv2 * gv;
}

// --------------------------------------------------------------------------
extern "C" void kernel_launch(void* const* d_in, const int* in_sizes, int n_in,
                              void* d_out, int out_size)
{
    const float* nf  = (const float*)d_in[0];   // node_features (N,64)
    const float* esh = (const float*)d_in[1];   // edge_sh (E,4)
    const float* emb = (const float*)d_in[2];   // edge_radial_emb (E,16)
    const float* w1  = (const float*)d_in[3];   // (16,64)
    const float* b1  = (const float*)d_in[4];   // (64)
    const float* w2  = (const float*)d_in[5];   // (64,1024)
    const float* b2  = (const float*)d_in[6];   // (1024)
    const float* lw0 = (const float*)d_in[7];   // (16,16)
    const float* lw1 = (const float*)d_in[8];   // (16,16)
    const int*   eix = (const int*)d_in[9];     // (2,E)

    int N = in_sizes[0] / 64;
    int E = in_sizes[2] / 16;
    float* out = (float*)d_out;

    int n4 = N * 16;  // float4 count of g_agg
    zero_kernel<<<(n4 + 255) / 256, 256>>>(n4);
    edge_kernel<<<(E + 15) / 16, 256>>>(nf, esh, emb, w1, b1, w2, b2, eix, E);
    node_kernel<<<(N * 16 + 255) / 256, 256>>>(nf, lw0, lw1, out, N);
}

// round 5
// speedup vs baseline: 4.4551x; 4.4551x over previous
#include <cuda_runtime.h>
#include <cstdint>

// ---------------------------------------------------------------------------
// TFN interaction block — tf32 tensor-core (mma.sync.m16n8k8) implementation.
//
//  prep_kernel: zero node accumulators + pre-round w2 to tf32 bits.
//  edge_kernel: CTA = 256 thr / 8 warps = 128 edges. Warp holds A = h tile
//               (16 edges x 64 k, tf32) in registers; w2 streamed in 64-col
//               chunks via cp.async double buffer; per-chunk tpw fragment is
//               contracted immediately into 40 per-thread output registers
//               (ps, t1, t2x/y/z per (edge-row, v-slot)); atomic scatter at end.
//  node_kernel: per-node linear + gated SiLU + residual.
// ---------------------------------------------------------------------------

#define NMAX 10000

__device__ float g_agg[NMAX * 64];    // [n][0:16]=agg_s, [n][16+u*3+i]=agg_v
__device__ float g_w2t[64 * 1024];    // w2 rounded to tf32 bit patterns

// --------------------------------------------------------------------------
__global__ void prep_kernel(const float* __restrict__ w2, int n4)
{
    int i = blockIdx.x * blockDim.x + threadIdx.x;
    if (i < n4) reinterpret_cast<float4*>(g_agg)[i] = make_float4(0.f, 0.f, 0.f, 0.f);
    if (i < 16384) {
        float4 v = reinterpret_cast<const float4*>(w2)[i];
        uint32_t r0, r1, r2, r3;
        asm("cvt.rna.tf32.f32 %0, %1;" : "=r"(r0) : "f"(v.x));
        asm("cvt.rna.tf32.f32 %0, %1;" : "=r"(r1) : "f"(v.y));
        asm("cvt.rna.tf32.f32 %0, %1;" : "=r"(r2) : "f"(v.z));
        asm("cvt.rna.tf32.f32 %0, %1;" : "=r"(r3) : "f"(v.w));
        float4 o;
        o.x = __uint_as_float(r0); o.y = __uint_as_float(r1);
        o.z = __uint_as_float(r2); o.w = __uint_as_float(r3);
        reinterpret_cast<float4*>(g_w2t)[i] = o;
    }
}

// --------------------------------------------------------------------------
// Shared memory layout (floats). Total 33408 floats = 133632 bytes (dynamic).
#define OFF_W2   0        // 2 x 64 x 72 = 9216   (double-buffered w2 chunk)
#define OFF_H    9216     // 128 x 72     = 9216   (tf32 h, padded stride 72)
#define OFF_CO   18432    // 6 x 128 x 16 = 12288  (coeffs [comp][e][u])
#define OFF_W1   30720    // 1024
#define OFF_B2   31744    // 1024
#define OFF_SH4  32768    // 128 x 4 = 512
#define OFF_DST  33280    // 128 ints
#define SMEM_FLOATS 33408
#define SMEM_BYTES  (SMEM_FLOATS * 4)
#define BUF_STRIDE 4608   // 64 rows x 72

__device__ __forceinline__ void cp_chunk(float* sbuf, int c, int tid)
{
    int row  = tid >> 2;            // 0..63  (k row)
    int part = (tid & 3) * 16;      // 0,16,32,48 (col offset)
    const float* gp = g_w2t + row * 1024 + c * 64 + part;
    uint32_t sp = (uint32_t)__cvta_generic_to_shared(sbuf + row * 72 + part);
#pragma unroll
    for (int i = 0; i < 4; i++)
        asm volatile("cp.async.cg.shared.global [%0], [%1], 16;"
                     :: "r"(sp + i * 16), "l"(gp + i * 4));
}

// --------------------------------------------------------------------------
__global__ __launch_bounds__(256, 1)
void edge_kernel(const float* __restrict__ nf,  const float* __restrict__ esh,
                 const float* __restrict__ emb, const float* __restrict__ w1,
                 const float* __restrict__ b1,  const float* __restrict__ b2,
                 const int*   __restrict__ eidx, int E)
{
    extern __shared__ float smem[];
    float* s_w2  = smem + OFF_W2;
    float* s_h   = smem + OFF_H;
    float* s_co  = smem + OFF_CO;
    float* s_w1  = smem + OFF_W1;
    float* s_b2  = smem + OFF_B2;
    float* s_sh4 = smem + OFF_SH4;
    int*   s_dst = (int*)(smem + OFF_DST);

    const int tid  = threadIdx.x;
    const int w    = tid >> 5;
    const int lane = tid & 31;
    const int gid  = lane >> 2;   // 0..7
    const int tig  = lane & 3;    // 0..3

    // stage w1 + b2 (one float4 each per thread)
    reinterpret_cast<float4*>(s_w1)[tid] = reinterpret_cast<const float4*>(w1)[tid];
    reinterpret_cast<float4*>(s_b2)[tid] = reinterpret_cast<const float4*>(b2)[tid];

    // prefetch w2 chunk 0
    cp_chunk(s_w2, 0, tid);
    asm volatile("cp.async.commit_group;");

    __syncthreads();   // s_w1 visible

    // ---------------- prologue: per-warp 16 edges ----------------
    const long long blockBase = (long long)blockIdx.x * 128;
    const float inv3 = 0.57735026919f;

    for (int r = 0; r < 16; r++) {
        const int eloc = w * 16 + r;
        long long e = blockBase + eloc;
        bool ok = (e < E);
        long long ec = ok ? e : 0;
        int src = eidx[ec];
        if (lane == 0) s_dst[eloc] = eidx[E + ec];

        // h = silu(emb @ w1 + b1), tf32-rounded into s_h
        float embv = (lane < 16 && ok) ? emb[ec * 16 + lane] : 0.f;
        float h0 = b1[lane], h1 = b1[lane + 32];
#pragma unroll
        for (int nb = 0; nb < 16; nb++) {
            float ev = __shfl_sync(0xffffffffu, embv, nb);
            h0 += ev * s_w1[nb * 64 + lane];
            h1 += ev * s_w1[nb * 64 + lane + 32];
        }
        h0 = h0 / (1.f + expf(-h0));
        h1 = h1 / (1.f + expf(-h1));
        if (!ok) { h0 = 0.f; h1 = 0.f; }
        uint32_t u0, u1;
        asm("cvt.rna.tf32.f32 %0, %1;" : "=r"(u0) : "f"(h0));
        asm("cvt.rna.tf32.f32 %0, %1;" : "=r"(u1) : "f"(h1));
        s_h[eloc * 72 + lane]      = __uint_as_float(u0);
        s_h[eloc * 72 + lane + 32] = __uint_as_float(u1);

        // coefficients (lane u < 16)
        if (lane < 16) {
            int u = lane;
            const float* nfp = nf + (long long)src * 64;
            float xs = nfp[u];
            float x0 = nfp[16 + u * 3 + 0];
            float x1 = nfp[16 + u * 3 + 1];
            float x2 = nfp[16 + u * 3 + 2];
            float shs = esh[ec * 4 + 0], sv0 = esh[ec * 4 + 1];
            float sv1 = esh[ec * 4 + 2], sv2 = esh[ec * 4 + 3];
            if (!ok) { xs = x0 = x1 = x2 = 0.f; shs = sv0 = sv1 = sv2 = 0.f; }
            s_co[0 * 2048 + eloc * 16 + u] = xs * shs;                                  // a_u  (W00 -> ps)
            s_co[1 * 2048 + eloc * 16 + u] = inv3 * (x0 * sv0 + x1 * sv1 + x2 * sv2);   // b_u  (W11 -> ps)
            s_co[2 * 2048 + eloc * 16 + u] = xs;                                        // W01 -> t1
            s_co[3 * 2048 + eloc * 16 + u] = x0 * shs;                                  // W10 -> t2x
            s_co[4 * 2048 + eloc * 16 + u] = x1 * shs;                                  // W10 -> t2y
            s_co[5 * 2048 + eloc * 16 + u] = x2 * shs;                                  // W10 -> t2z
            if (u == 0) {
                s_sh4[eloc * 4 + 0] = shs; s_sh4[eloc * 4 + 1] = sv0;
                s_sh4[eloc * 4 + 2] = sv1; s_sh4[eloc * 4 + 3] = sv2;
            }
        }
    }
    __syncthreads();   // s_h / s_co / s_dst / s_sh4 visible

    // A fragments: h tile 16x64 (rows gid, gid+8), tf32 bits
    uint32_t aF[8][4];
    {
        const float* h0p = s_h + (w * 16 + gid) * 72;
        const float* h8p = s_h + (w * 16 + gid + 8) * 72;
#pragma unroll
        for (int kt = 0; kt < 8; kt++) {
            aF[kt][0] = __float_as_uint(h0p[kt * 8 + tig]);
            aF[kt][1] = __float_as_uint(h8p[kt * 8 + tig]);
            aF[kt][2] = __float_as_uint(h0p[kt * 8 + tig + 4]);
            aF[kt][3] = __float_as_uint(h8p[kt * 8 + tig + 4]);
        }
    }

    // persistent contraction outputs: [row(2)][vslot(4)][comp(5: ps,t1,t2x,t2y,t2z)]
    float out[2][4][5];
#pragma unroll
    for (int a = 0; a < 2; a++)
#pragma unroll
        for (int s = 0; s < 4; s++)
#pragma unroll
            for (int q = 0; q < 5; q++) out[a][s][q] = 0.f;

    const int e0 = w * 16 + gid, e1 = e0 + 8;

    // ---------------- main loop: 16 chunks of 64 w2 columns ----------------
    for (int c = 0; c < 16; c++) {
        __syncthreads();                       // prev users done with buf (c+1)&1
        if (c + 1 < 16) {
            cp_chunk(s_w2 + ((c + 1) & 1) * BUF_STRIDE, c + 1, tid);
            asm volatile("cp.async.commit_group;");
            asm volatile("cp.async.wait_group 1;");
        } else {
            asm volatile("cp.async.wait_group 0;");
        }
        __syncthreads();                       // chunk c visible to all

        const float* B = s_w2 + (c & 1) * BUF_STRIDE;

        // accumulators init = b2[j] (broadcast over rows)
        float acc[8][4];
#pragma unroll
        for (int t = 0; t < 8; t++) {
            float bz0 = s_b2[c * 64 + t * 8 + tig * 2];
            float bz1 = s_b2[c * 64 + t * 8 + tig * 2 + 1];
            acc[t][0] = bz0; acc[t][1] = bz1; acc[t][2] = bz0; acc[t][3] = bz1;
        }

#pragma unroll
        for (int kt = 0; kt < 8; kt++) {
            uint32_t bf[8][2];
#pragma unroll
            for (int t = 0; t < 8; t++) {
                bf[t][0] = __float_as_uint(B[(kt * 8 + tig) * 72 + t * 8 + gid]);
                bf[t][1] = __float_as_uint(B[(kt * 8 + tig + 4) * 72 + t * 8 + gid]);
            }
#pragma unroll
            for (int t = 0; t < 8; t++) {
                asm volatile(
                    "mma.sync.aligned.m16n8k8.row.col.f32.tf32.tf32.f32 "
                    "{%0,%1,%2,%3}, {%4,%5,%6,%7}, {%8,%9}, {%0,%1,%2,%3};"
                    : "+f"(acc[t][0]), "+f"(acc[t][1]), "+f"(acc[t][2]), "+f"(acc[t][3])
                    : "r"(aF[kt][0]), "r"(aF[kt][1]), "r"(aF[kt][2]), "r"(aF[kt][3]),
                      "r"(bf[t][0]), "r"(bf[t][1]));
            }
        }

        // ------------- epilogue: contract chunk into out regs -------------
        const int gq = c >> 2;            // which W block
        const int ub = (c & 3) * 4;       // u base for this chunk

#define EPI_ARM(COMP, OC)                                                     \
        {                                                                     \
            float cR0[4], cR1[4];                                             \
            _Pragma("unroll")                                                 \
            for (int uu = 0; uu < 4; uu++) {                                  \
                cR0[uu] = s_co[(COMP) * 2048 + e0 * 16 + ub + uu];            \
                cR1[uu] = s_co[(COMP) * 2048 + e1 * 16 + ub + uu];            \
            }                                                                 \
            _Pragma("unroll")                                                 \
            for (int t = 0; t < 8; t++) {                                     \
                const int uu = t >> 1, sb = (t & 1) * 2;                      \
                out[0][sb    ][(OC)] += cR0[uu] * acc[t][0];                  \
                out[0][sb + 1][(OC)] += cR0[uu] * acc[t][1];                  \
                out[1][sb    ][(OC)] += cR1[uu] * acc[t][2];                  \
                out[1][sb + 1][(OC)] += cR1[uu] * acc[t][3];                  \
            }                                                                 \
        }

        if (gq == 0)      EPI_ARM(0, 0)       // W00: a_u -> ps
        else if (gq == 1) EPI_ARM(2, 1)       // W01: xs_u -> t1
        else if (gq == 3) EPI_ARM(1, 0)       // W11: b_u -> ps
        else {                                // W10: x_i*shs -> t2i
            float c0r[4][3], c1r[4][3];
#pragma unroll
            for (int uu = 0; uu < 4; uu++)
#pragma unroll
                for (int i = 0; i < 3; i++) {
                    c0r[uu][i] = s_co[(3 + i) * 2048 + e0 * 16 + ub + uu];
                    c1r[uu][i] = s_co[(3 + i) * 2048 + e1 * 16 + ub + uu];
                }
#pragma unroll
            for (int t = 0; t < 8; t++) {
                const int uu = t >> 1, sb = (t & 1) * 2;
#pragma unroll
                for (int i = 0; i < 3; i++) {
                    out[0][sb    ][2 + i] += c0r[uu][i] * acc[t][0];
                    out[0][sb + 1][2 + i] += c0r[uu][i] * acc[t][1];
                    out[1][sb    ][2 + i] += c1r[uu][i] * acc[t][2];
                    out[1][sb + 1][2 + i] += c1r[uu][i] * acc[t][3];
                }
            }
        }
#undef EPI_ARM
    }

    // ---------------- scatter: atomic add into g_agg ----------------
    const float alpha = 0.17677669529f;   // 1/sqrt(2*MUL)
#pragma unroll
    for (int row = 0; row < 2; row++) {
        const int eloc = w * 16 + gid + row * 8;
        long long e = blockBase + eloc;
        if (e < E) {
            int dst = s_dst[eloc];
            float sv0 = s_sh4[eloc * 4 + 1];
            float sv1 = s_sh4[eloc * 4 + 2];
            float sv2 = s_sh4[eloc * 4 + 3];
            float* dp = g_agg + (long long)dst * 64;
#pragma unroll
            for (int s = 0; s < 4; s++) {
                const int v = (s >> 1) * 8 + tig * 2 + (s & 1);
                atomicAdd(dp + v, alpha * out[row][s][0]);
                atomicAdd(dp + 16 + v * 3 + 0, alpha * (out[row][s][1] * sv0 + out[row][s][2]));
                atomicAdd(dp + 16 + v * 3 + 1, alpha * (out[row][s][1] * sv1 + out[row][s][3]));
                atomicAdd(dp + 16 + v * 3 + 2, alpha * (out[row][s][1] * sv2 + out[row][s][4]));
            }
        }
    }
}

// --------------------------------------------------------------------------
__global__ void node_kernel(const float* __restrict__ nf,
                            const float* __restrict__ lw0,
                            const float* __restrict__ lw1,
                            float* __restrict__ out, int N)
{
    int idx = blockIdx.x * blockDim.x + threadIdx.x;
    int n = idx >> 4, v = idx & 15;
    if (n >= N) return;

    const float* ag = g_agg + (long long)n * 64;
    float ts = 0.f, tv0 = 0.f, tv1 = 0.f, tv2 = 0.f;
#pragma unroll
    for (int u = 0; u < 16; u++) {
        float l0 = __ldg(lw0 + u * 16 + v);
        float l1 = __ldg(lw1 + u * 16 + v);
        ts  += ag[u] * l0;
        tv0 += ag[16 + u * 3 + 0] * l1;
        tv1 += ag[16 + u * 3 + 1] * l1;
        tv2 += ag[16 + u * 3 + 2] * l1;
    }
    const float s = 0.25f;   // 1/sqrt(MUL)
    ts *= s; tv0 *= s; tv1 *= s; tv2 *= s;

    const float eps = 1e-8f;
    float ns = fabsf(ts);
    float gs = ns / ((1.f + expf(-ns)) * (ns + eps));
    float nv = sqrtf(tv0 * tv0 + tv1 * tv1 + tv2 * tv2);
    float gv = nv / ((1.f + expf(-nv)) * (nv + eps));

    const float* nfp = nf + (long long)n * 64;
    float*       op  = out + (long long)n * 64;
    op[v]              = nfp[v]              + ts  * gs;
    op[16 + v * 3 + 0] = nfp[16 + v * 3 + 0] + tv0 * gv;
    op[16 + v * 3 + 1] = nfp[16 + v * 3 + 1] + tv1 * gv;
    op[16 + v * 3 + 2] = nfp[16 + v * 3 + 2] + tv2 * gv;
}

// --------------------------------------------------------------------------
extern "C" void kernel_launch(void* const* d_in, const int* in_sizes, int n_in,
                              void* d_out, int out_size)
{
    const float* nf  = (const float*)d_in[0];   // node_features (N,64)
    const float* esh = (const float*)d_in[1];   // edge_sh (E,4)
    const float* emb = (const float*)d_in[2];   // edge_radial_emb (E,16)
    const float* w1  = (const float*)d_in[3];   // (16,64)
    const float* b1  = (const float*)d_in[4];   // (64)
    const float* w2  = (const float*)d_in[5];   // (64,1024)
    const float* b2  = (const float*)d_in[6];   // (1024)
    const float* lw0 = (const float*)d_in[7];   // (16,16)
    const float* lw1 = (const float*)d_in[8];   // (16,16)
    const int*   eix = (const int*)d_in[9];     // (2,E)

    int N = in_sizes[0] / 64;
    int E = in_sizes[2] / 16;
    float* out = (float*)d_out;

    cudaFuncSetAttribute(edge_kernel,
                         cudaFuncAttributeMaxDynamicSharedMemorySize, SMEM_BYTES);

    int n4 = N * 16;
    int prepN = (n4 > 16384) ? n4 : 16384;
    prep_kernel<<<(prepN + 255) / 256, 256>>>(w2, n4);
    edge_kernel<<<(E + 127) / 128, 256, SMEM_BYTES>>>(nf, esh, emb, w1, b1, b2, eix, E);
    node_kernel<<<(N * 16 + 255) / 256, 256>>>(nf, lw0, lw1, out, N);
}

// round 6
// speedup vs baseline: 5.2266x; 1.1732x over previous
#include <cuda_runtime.h>
#include <cuda_fp16.h>
#include <cstdint>

// ---------------------------------------------------------------------------
// TFN interaction block — fp16 tensor-core (mma.sync.m16n8k16.f16.f32).
//
//  prep_kernel: zero node accumulators + convert w2 to half, transposed [j][k].
//  edge_kernel: CTA = 256 thr / 8 warps = 128 edges, 2 CTAs/SM.
//               Warp holds A = h tile (16 edges x 64 k, half) in registers;
//               w2^T streamed in 64-col chunks via cp.async double buffer;
//               per-chunk tpw fragment contracted immediately into 40
//               per-thread output registers; atomic scatter at end.
//  node_kernel: per-node linear + gated SiLU + residual.
// ---------------------------------------------------------------------------

#define NMAX 10000

__device__ float  g_agg[NMAX * 64];   // [n][0:16]=agg_s, [n][16+u*3+i]=agg_v
__device__ __half g_w2h[1024 * 64];   // w2 transposed: [j][k] half

// --------------------------------------------------------------------------
__global__ void prep_kernel(const float* __restrict__ w2, int n4)
{
    int i = blockIdx.x * blockDim.x + threadIdx.x;
    if (i < n4) reinterpret_cast<float4*>(g_agg)[i] = make_float4(0.f, 0.f, 0.f, 0.f);
    if (i < 65536) {
        int k = i >> 10, j = i & 1023;          // coalesced read of w2[k][j]
        g_w2h[j * 64 + k] = __float2half_rn(w2[i]);
    }
}

// --------------------------------------------------------------------------
// Shared memory layout (bytes). Total 98816 B -> 2 CTAs/SM.
#define OFF_W2   0        // 2 x 64 x 72 halves = 18432 B (double-buffered w2^T chunk)
#define OFF_H    18432    // 128 x 72 halves    = 18432 B (h, padded row 144B)
#define OFF_CO   36864    // 128 x 100 floats   = 51200 B (coeffs [e][comp*16+u], pad 4)
#define OFF_W1   88064    // 1024 f = 4096 B
#define OFF_B2   92160    // 1024 f = 4096 B
#define OFF_SH4  96256    // 128 x 4 f = 2048 B
#define OFF_DST  98304    // 128 int = 512 B
#define SMEM_BYTES 98816
#define BUF_STRIDE_H 4608   // 64 rows x 72 halves

__device__ __forceinline__ void cp_chunk(__half* sbuf, int c, int tid)
{
    int row  = tid >> 2;          // 0..63  (chunk col j)
    int quad = tid & 3;           // 16-half (32B) sub-block
    const __half* gp = g_w2h + (c * 64 + row) * 64 + quad * 16;
    uint32_t sp = (uint32_t)__cvta_generic_to_shared(sbuf + row * 72 + quad * 16);
    asm volatile("cp.async.cg.shared.global [%0], [%1], 16;" :: "r"(sp),      "l"(gp));
    asm volatile("cp.async.cg.shared.global [%0], [%1], 16;" :: "r"(sp + 16), "l"(gp + 8));
}

// --------------------------------------------------------------------------
__global__ __launch_bounds__(256, 2)
void edge_kernel(const float* __restrict__ nf,  const float* __restrict__ esh,
                 const float* __restrict__ emb, const float* __restrict__ w1,
                 const float* __restrict__ b1,  const float* __restrict__ b2,
                 const int*   __restrict__ eidx, int E)
{
    extern __shared__ __align__(16) char smem_raw[];
    __half* s_w2  = (__half*)(smem_raw + OFF_W2);
    __half* s_h   = (__half*)(smem_raw + OFF_H);
    float*  s_co  = (float*)(smem_raw + OFF_CO);
    float*  s_w1  = (float*)(smem_raw + OFF_W1);
    float*  s_b2  = (float*)(smem_raw + OFF_B2);
    float*  s_sh4 = (float*)(smem_raw + OFF_SH4);
    int*    s_dst = (int*)(smem_raw + OFF_DST);

    const int tid  = threadIdx.x;
    const int w    = tid >> 5;
    const int lane = tid & 31;
    const int gid  = lane >> 2;   // 0..7
    const int tig  = lane & 3;    // 0..3

    // stage w1 + b2 (one float4 each per thread)
    reinterpret_cast<float4*>(s_w1)[tid] = reinterpret_cast<const float4*>(w1)[tid];
    reinterpret_cast<float4*>(s_b2)[tid] = reinterpret_cast<const float4*>(b2)[tid];

    // prefetch w2 chunk 0
    cp_chunk(s_w2, 0, tid);
    asm volatile("cp.async.commit_group;");

    __syncthreads();   // s_w1 visible

    // ---------------- prologue: per-warp 16 edges ----------------
    const long long blockBase = (long long)blockIdx.x * 128;
    const float inv3 = 0.57735026919f;

    for (int r = 0; r < 16; r++) {
        const int eloc = w * 16 + r;
        long long e = blockBase + eloc;
        bool ok = (e < E);
        long long ec = ok ? e : 0;
        int src = eidx[ec];
        if (lane == 0) s_dst[eloc] = eidx[E + ec];

        // h = silu(emb @ w1 + b1) -> half
        float embv = (lane < 16 && ok) ? emb[ec * 16 + lane] : 0.f;
        float h0 = b1[lane], h1 = b1[lane + 32];
#pragma unroll
        for (int nb = 0; nb < 16; nb++) {
            float ev = __shfl_sync(0xffffffffu, embv, nb);
            h0 += ev * s_w1[nb * 64 + lane];
            h1 += ev * s_w1[nb * 64 + lane + 32];
        }
        h0 = h0 / (1.f + expf(-h0));
        h1 = h1 / (1.f + expf(-h1));
        if (!ok) { h0 = 0.f; h1 = 0.f; }
        s_h[eloc * 72 + lane]      = __float2half_rn(h0);
        s_h[eloc * 72 + lane + 32] = __float2half_rn(h1);

        // coefficients (lane u < 16); layout [e][comp*16+u], edge stride 100
        if (lane < 16) {
            int u = lane;
            const float* nfp = nf + (long long)src * 64;
            float xs = nfp[u];
            float x0 = nfp[16 + u * 3 + 0];
            float x1 = nfp[16 + u * 3 + 1];
            float x2 = nfp[16 + u * 3 + 2];
            float shs = esh[ec * 4 + 0], sv0 = esh[ec * 4 + 1];
            float sv1 = esh[ec * 4 + 2], sv2 = esh[ec * 4 + 3];
            if (!ok) { xs = x0 = x1 = x2 = 0.f; shs = sv0 = sv1 = sv2 = 0.f; }
            float* cp = s_co + eloc * 100;
            cp[0 * 16 + u] = xs * shs;                                  // a_u  (W00 -> ps)
            cp[1 * 16 + u] = inv3 * (x0 * sv0 + x1 * sv1 + x2 * sv2);   // b_u  (W11 -> ps)
            cp[2 * 16 + u] = xs;                                        // W01 -> t1
            cp[3 * 16 + u] = x0 * shs;                                  // W10 -> t2x
            cp[4 * 16 + u] = x1 * shs;                                  // W10 -> t2y
            cp[5 * 16 + u] = x2 * shs;                                  // W10 -> t2z
            if (u == 0) {
                s_sh4[eloc * 4 + 0] = shs; s_sh4[eloc * 4 + 1] = sv0;
                s_sh4[eloc * 4 + 2] = sv1; s_sh4[eloc * 4 + 3] = sv2;
            }
        }
    }
    __syncthreads();   // s_h / s_co / s_dst / s_sh4 visible

    // A fragments (m16n8k16): rows gid, gid+8; k pairs packed as u32
    uint32_t aF[4][4];
    {
        const __half* hp0 = s_h + (w * 16 + gid) * 72;
        const __half* hp8 = s_h + (w * 16 + gid + 8) * 72;
#pragma unroll
        for (int kt = 0; kt < 4; kt++) {
            aF[kt][0] = *(const uint32_t*)(hp0 + kt * 16 + tig * 2);
            aF[kt][1] = *(const uint32_t*)(hp8 + kt * 16 + tig * 2);
            aF[kt][2] = *(const uint32_t*)(hp0 + kt * 16 + tig * 2 + 8);
            aF[kt][3] = *(const uint32_t*)(hp8 + kt * 16 + tig * 2 + 8);
        }
    }

    // persistent contraction outputs: [row(2)][vslot(4)][comp(5: ps,t1,t2x,t2y,t2z)]
    float out[2][4][5];
#pragma unroll
    for (int a = 0; a < 2; a++)
#pragma unroll
        for (int s = 0; s < 4; s++)
#pragma unroll
            for (int q = 0; q < 5; q++) out[a][s][q] = 0.f;

    const int e0 = w * 16 + gid, e1 = e0 + 8;

    // ---------------- main loop: 16 chunks of 64 w2 columns ----------------
    for (int c = 0; c < 16; c++) {
        __syncthreads();                       // prev users done with buf (c+1)&1
        if (c + 1 < 16) {
            cp_chunk(s_w2 + ((c + 1) & 1) * BUF_STRIDE_H, c + 1, tid);
            asm volatile("cp.async.commit_group;");
            asm volatile("cp.async.wait_group 1;");
        } else {
            asm volatile("cp.async.wait_group 0;");
        }
        __syncthreads();                       // chunk c visible to all

        const __half* B = s_w2 + (c & 1) * BUF_STRIDE_H;

        // accumulators init = b2[j] (broadcast over rows)
        float acc[8][4];
#pragma unroll
        for (int t = 0; t < 8; t++) {
            float bz0 = s_b2[c * 64 + t * 8 + tig * 2];
            float bz1 = s_b2[c * 64 + t * 8 + tig * 2 + 1];
            acc[t][0] = bz0; acc[t][1] = bz1; acc[t][2] = bz0; acc[t][3] = bz1;
        }

#pragma unroll
        for (int kt = 0; kt < 4; kt++) {
            uint32_t bf[8][2];
#pragma unroll
            for (int t = 0; t < 8; t++) {
                const __half* bp = B + (t * 8 + gid) * 72 + kt * 16 + tig * 2;
                bf[t][0] = *(const uint32_t*)(bp);
                bf[t][1] = *(const uint32_t*)(bp + 8);
            }
#pragma unroll
            for (int t = 0; t < 8; t++) {
                asm volatile(
                    "mma.sync.aligned.m16n8k16.row.col.f32.f16.f16.f32 "
                    "{%0,%1,%2,%3}, {%4,%5,%6,%7}, {%8,%9}, {%0,%1,%2,%3};"
                    : "+f"(acc[t][0]), "+f"(acc[t][1]), "+f"(acc[t][2]), "+f"(acc[t][3])
                    : "r"(aF[kt][0]), "r"(aF[kt][1]), "r"(aF[kt][2]), "r"(aF[kt][3]),
                      "r"(bf[t][0]), "r"(bf[t][1]));
            }
        }

        // ------------- epilogue: contract chunk into out regs -------------
        const int gq = c >> 2;            // which W block
        const int ub = (c & 3) * 4;       // u base for this chunk

#define EPI_ARM(COMP, OC)                                                     \
        {                                                                     \
            float4 c4a = *(const float4*)(s_co + e0 * 100 + (COMP) * 16 + ub);\
            float4 c4b = *(const float4*)(s_co + e1 * 100 + (COMP) * 16 + ub);\
            float cR0[4] = {c4a.x, c4a.y, c4a.z, c4a.w};                      \
            float cR1[4] = {c4b.x, c4b.y, c4b.z, c4b.w};                      \
            _Pragma("unroll")                                                 \
            for (int t = 0; t < 8; t++) {                                     \
                const int uu = t >> 1, sb = (t & 1) * 2;                      \
                out[0][sb    ][(OC)] += cR0[uu] * acc[t][0];                  \
                out[0][sb + 1][(OC)] += cR0[uu] * acc[t][1];                  \
                out[1][sb    ][(OC)] += cR1[uu] * acc[t][2];                  \
                out[1][sb + 1][(OC)] += cR1[uu] * acc[t][3];                  \
            }                                                                 \
        }

        if (gq == 0)      EPI_ARM(0, 0)       // W00: a_u -> ps
        else if (gq == 1) EPI_ARM(2, 1)       // W01: xs_u -> t1
        else if (gq == 3) EPI_ARM(1, 0)       // W11: b_u -> ps
        else {                                // W10: x_i*shs -> t2i
            EPI_ARM(3, 2)
            EPI_ARM(4, 3)
            EPI_ARM(5, 4)
        }
#undef EPI_ARM
    }

    // ---------------- scatter: atomic add into g_agg ----------------
    const float alpha = 0.17677669529f;   // 1/sqrt(2*MUL)
#pragma unroll
    for (int row = 0; row < 2; row++) {
        const int eloc = w * 16 + gid + row * 8;
        long long e = blockBase + eloc;
        if (e < E) {
            int dst = s_dst[eloc];
            float sv0 = s_sh4[eloc * 4 + 1];
            float sv1 = s_sh4[eloc * 4 + 2];
            float sv2 = s_sh4[eloc * 4 + 3];
            float* dp = g_agg + (long long)dst * 64;
#pragma unroll
            for (int s = 0; s < 4; s++) {
                const int v = (s >> 1) * 8 + tig * 2 + (s & 1);
                atomicAdd(dp + v, alpha * out[row][s][0]);
                atomicAdd(dp + 16 + v * 3 + 0, alpha * (out[row][s][1] * sv0 + out[row][s][2]));
                atomicAdd(dp + 16 + v * 3 + 1, alpha * (out[row][s][1] * sv1 + out[row][s][3]));
                atomicAdd(dp + 16 + v * 3 + 2, alpha * (out[row][s][1] * sv2 + out[row][s][4]));
            }
        }
    }
}

// --------------------------------------------------------------------------
__global__ void node_kernel(const float* __restrict__ nf,
                            const float* __restrict__ lw0,
                            const float* __restrict__ lw1,
                            float* __restrict__ out, int N)
{
    int idx = blockIdx.x * blockDim.x + threadIdx.x;
    int n = idx >> 4, v = idx & 15;
    if (n >= N) return;

    const float* ag = g_agg + (long long)n * 64;
    float ts = 0.f, tv0 = 0.f, tv1 = 0.f, tv2 = 0.f;
#pragma unroll
    for (int u = 0; u < 16; u++) {
        float l0 = __ldg(lw0 + u * 16 + v);
        float l1 = __ldg(lw1 + u * 16 + v);
        ts  += ag[u] * l0;
        tv0 += ag[16 + u * 3 + 0] * l1;
        tv1 += ag[16 + u * 3 + 1] * l1;
        tv2 += ag[16 + u * 3 + 2] * l1;
    }
    const float s = 0.25f;   // 1/sqrt(MUL)
    ts *= s; tv0 *= s; tv1 *= s; tv2 *= s;

    const float eps = 1e-8f;
    float ns = fabsf(ts);
    float gs = ns / ((1.f + expf(-ns)) * (ns + eps));
    float nv = sqrtf(tv0 * tv0 + tv1 * tv1 + tv2 * tv2);
    float gv = nv / ((1.f + expf(-nv)) * (nv + eps));

    const float* nfp = nf + (long long)n * 64;
    float*       op  = out + (long long)n * 64;
    op[v]              = nfp[v]              + ts  * gs;
    op[16 + v * 3 + 0] = nfp[16 + v * 3 + 0] + tv0 * gv;
    op[16 + v * 3 + 1] = nfp[16 + v * 3 + 1] + tv1 * gv;
    op[16 + v * 3 + 2] = nfp[16 + v * 3 + 2] + tv2 * gv;
}

// --------------------------------------------------------------------------
extern "C" void kernel_launch(void* const* d_in, const int* in_sizes, int n_in,
                              void* d_out, int out_size)
{
    const float* nf  = (const float*)d_in[0];   // node_features (N,64)
    const float* esh = (const float*)d_in[1];   // edge_sh (E,4)
    const float* emb = (const float*)d_in[2];   // edge_radial_emb (E,16)
    const float* w1  = (const float*)d_in[3];   // (16,64)
    const float* b1  = (const float*)d_in[4];   // (64)
    const float* w2  = (const float*)d_in[5];   // (64,1024)
    const float* b2  = (const float*)d_in[6];   // (1024)
    const float* lw0 = (const float*)d_in[7];   // (16,16)
    const float* lw1 = (const float*)d_in[8];   // (16,16)
    const int*   eix = (const int*)d_in[9];     // (2,E)

    int N = in_sizes[0] / 64;
    int E = in_sizes[2] / 16;
    float* out = (float*)d_out;

    cudaFuncSetAttribute(edge_kernel,
                         cudaFuncAttributeMaxDynamicSharedMemorySize, SMEM_BYTES);

    int n4 = N * 16;
    int prepN = (n4 > 65536) ? n4 : 65536;
    prep_kernel<<<(prepN + 255) / 256, 256>>>(w2, n4);
    edge_kernel<<<(E + 127) / 128, 256, SMEM_BYTES>>>(nf, esh, emb, w1, b1, b2, eix, E);
    node_kernel<<<(N * 16 + 255) / 256, 256>>>(nf, lw0, lw1, out, N);
}

// round 10
// speedup vs baseline: 8.4796x; 1.6224x over previous
#include <cuda_runtime.h>
#include <cuda_fp16.h>
#include <cstdint>

// ---------------------------------------------------------------------------
// TFN interaction block — fp16 mma.m16n8k16 + cp.async.bulk + ldmatrix.
//
//  prep_kernel: zero accumulators; build g_w2s = w2 as half, transposed [j][k],
//               chunk-contiguous (16 chunks x 8KB) with XOR-16B swizzle baked in.
//  edge_kernel: CTA = 256 thr / 8 warps = 128 edges, 2 CTAs/SM.
//               Double-buffered 8KB w2 chunks: ONE cp.async.bulk per chunk
//               (completion via full-mbarrier), buffer recycling guarded by the
//               proven __syncthreads pattern (no empty barriers -> deterministic).
//               B fragments via ldmatrix.x4; per-chunk tpw contracted into 40
//               per-thread output registers; atomic scatter at end.
//  node_kernel: per-node linear + gated SiLU + residual.
// ---------------------------------------------------------------------------

#define NMAX 10000

__device__ float  g_agg[NMAX * 64];   // [n][0:16]=agg_s, [n][16+u*3+i]=agg_v
__device__ __half g_w2s[16 * 4096];   // swizzled w2^T, chunk-contiguous

// --------------------------------------------------------------------------
__global__ void prep_kernel(const float* __restrict__ w2, int n4)
{
    int i = blockIdx.x * blockDim.x + threadIdx.x;
    if (i < n4) reinterpret_cast<float4*>(g_agg)[i] = make_float4(0.f, 0.f, 0.f, 0.f);
    if (i < 65536) {
        int k = i >> 10, j = i & 1023;        // coalesced read of w2[k][j]
        int c = j >> 6, r = j & 63;
        int idx = c * 4096 + r * 64 + (k ^ ((r & 7) * 8));   // 16B-granule XOR swizzle
        g_w2s[idx] = __float2half_rn(w2[i]);
    }
}

// --------------------------------------------------------------------------
// Shared memory layout (bytes). Total 96800 B -> 2 CTAs/SM.
#define OFF_W2   0         // 2 x 8192 = 16384  (double-buffered w2 chunk, swizzled)
#define OFF_H    16384     // 128 x 72 halves = 18432
#define OFF_CO   34816     // 128 x 100 floats = 51200
#define OFF_W1   86016     // 4096
#define OFF_B2   90112     // 4096
#define OFF_SH4  94208     // 2048
#define OFF_DST  96256     // 512
#define OFF_MB   96768     // full[b] mbarrier @ +b*16
#define SMEM_BYTES 96800
#define CHUNK_BYTES 8192

__device__ __forceinline__ void mb_init(uint32_t a, uint32_t cnt) {
    asm volatile("mbarrier.init.shared.b64 [%0], %1;" :: "r"(a), "r"(cnt) : "memory");
}
__device__ __forceinline__ void mb_expect_tx(uint32_t a, uint32_t bytes) {
    asm volatile("mbarrier.arrive.expect_tx.shared.b64 _, [%0], %1;" :: "r"(a), "r"(bytes) : "memory");
}
__device__ __forceinline__ void mb_wait(uint32_t a, uint32_t parity) {
    uint32_t done;
    asm volatile("{\n\t.reg .pred p;\n\t"
                 "mbarrier.try_wait.parity.acquire.cta.shared::cta.b64 p, [%1], %2;\n\t"
                 "selp.b32 %0, 1, 0, p;\n\t}"
                 : "=r"(done) : "r"(a), "r"(parity) : "memory");
    if (!done) {
        asm volatile("{\n\t.reg .pred P1;\n\t"
                     "W_%=:\n\t"
                     "mbarrier.try_wait.parity.acquire.cta.shared::cta.b64 P1, [%0], %1, 0x989680;\n\t"
                     "@P1 bra.uni D_%=;\n\t"
                     "bra.uni W_%=;\n\t"
                     "D_%=:\n\t}"
                     :: "r"(a), "r"(parity) : "memory");
    }
}
__device__ __forceinline__ void bulk_cp(uint32_t dst, const void* src, uint32_t mbar) {
    asm volatile("cp.async.bulk.shared::cta.global.mbarrier::complete_tx::bytes "
                 "[%0], [%1], %2, [%3];"
                 :: "r"(dst), "l"(src), "r"((uint32_t)CHUNK_BYTES), "r"(mbar) : "memory");
}

// --------------------------------------------------------------------------
__global__ __launch_bounds__(256, 2)
void edge_kernel(const float* __restrict__ nf,  const float* __restrict__ esh,
                 const float* __restrict__ emb, const float* __restrict__ w1,
                 const float* __restrict__ b1,  const float* __restrict__ b2,
                 const int*   __restrict__ eidx, int E)
{
    extern __shared__ __align__(16) char smem_raw[];
    __half* s_h   = (__half*)(smem_raw + OFF_H);
    float*  s_co  = (float*)(smem_raw + OFF_CO);
    float*  s_w1  = (float*)(smem_raw + OFF_W1);
    float*  s_b2  = (float*)(smem_raw + OFF_B2);
    float*  s_sh4 = (float*)(smem_raw + OFF_SH4);
    int*    s_dst = (int*)(smem_raw + OFF_DST);

    const uint32_t smem_u32 = (uint32_t)__cvta_generic_to_shared(smem_raw);
    const uint32_t w2_u32   = smem_u32 + OFF_W2;
    const uint32_t mb_u32   = smem_u32 + OFF_MB;

    const int tid  = threadIdx.x;
    const int w    = tid >> 5;
    const int lane = tid & 31;
    const int gid  = lane >> 2;   // 0..7
    const int tig  = lane & 3;    // 0..3

    // stage w1 + b2 (one float4 each per thread)
    reinterpret_cast<float4*>(s_w1)[tid] = reinterpret_cast<const float4*>(w1)[tid];
    reinterpret_cast<float4*>(s_b2)[tid] = reinterpret_cast<const float4*>(b2)[tid];

    if (tid == 0) {
        mb_init(mb_u32,      1);
        mb_init(mb_u32 + 16, 1);
    }
    __syncthreads();   // mbarriers + s_w1 visible to all (incl. bulk engine ordering)

    // kick off chunk 0 (overlaps the prologue)
    if (tid == 0) {
        mb_expect_tx(mb_u32, CHUNK_BYTES);
        bulk_cp(w2_u32, g_w2s, mb_u32);
    }

    // ---------------- prologue: per-warp 16 edges ----------------
    const long long blockBase = (long long)blockIdx.x * 128;
    const float inv3 = 0.57735026919f;

    for (int r = 0; r < 16; r++) {
        const int eloc = w * 16 + r;
        long long e = blockBase + eloc;
        bool ok = (e < E);
        long long ec = ok ? e : 0;
        int src = eidx[ec];
        if (lane == 0) s_dst[eloc] = eidx[E + ec];

        // h = silu(emb @ w1 + b1) -> half
        float embv = (lane < 16 && ok) ? emb[ec * 16 + lane] : 0.f;
        float h0 = b1[lane], h1 = b1[lane + 32];
#pragma unroll
        for (int nb = 0; nb < 16; nb++) {
            float ev = __shfl_sync(0xffffffffu, embv, nb);
            h0 += ev * s_w1[nb * 64 + lane];
            h1 += ev * s_w1[nb * 64 + lane + 32];
        }
        h0 = h0 / (1.f + expf(-h0));
        h1 = h1 / (1.f + expf(-h1));
        if (!ok) { h0 = 0.f; h1 = 0.f; }
        s_h[eloc * 72 + lane]      = __float2half_rn(h0);
        s_h[eloc * 72 + lane + 32] = __float2half_rn(h1);

        // coefficients (lane u < 16); layout [e][comp*16+u], edge stride 100
        if (lane < 16) {
            int u = lane;
            const float* nfp = nf + (long long)src * 64;
            float xs = nfp[u];
            float x0 = nfp[16 + u * 3 + 0];
            float x1 = nfp[16 + u * 3 + 1];
            float x2 = nfp[16 + u * 3 + 2];
            float shs = esh[ec * 4 + 0], sv0 = esh[ec * 4 + 1];
            float sv1 = esh[ec * 4 + 2], sv2 = esh[ec * 4 + 3];
            if (!ok) { xs = x0 = x1 = x2 = 0.f; shs = sv0 = sv1 = sv2 = 0.f; }
            float* cp = s_co + eloc * 100;
            cp[0 * 16 + u] = xs * shs;                                  // a_u  (W00 -> ps)
            cp[1 * 16 + u] = inv3 * (x0 * sv0 + x1 * sv1 + x2 * sv2);   // b_u  (W11 -> ps)
            cp[2 * 16 + u] = xs;                                        // W01 -> t1
            cp[3 * 16 + u] = x0 * shs;                                  // W10 -> t2x
            cp[4 * 16 + u] = x1 * shs;                                  // W10 -> t2y
            cp[5 * 16 + u] = x2 * shs;                                  // W10 -> t2z
            if (u == 0) {
                s_sh4[eloc * 4 + 0] = shs; s_sh4[eloc * 4 + 1] = sv0;
                s_sh4[eloc * 4 + 2] = sv1; s_sh4[eloc * 4 + 3] = sv2;
            }
        }
    }
    __syncthreads();   // s_h / s_co / s_dst / s_sh4 visible

    // A fragments (m16n8k16): rows gid, gid+8; k pairs packed as u32
    uint32_t aF[4][4];
    {
        const __half* hp0 = s_h + (w * 16 + gid) * 72;
        const __half* hp8 = s_h + (w * 16 + gid + 8) * 72;
#pragma unroll
        for (int kt = 0; kt < 4; kt++) {
            aF[kt][0] = *(const uint32_t*)(hp0 + kt * 16 + tig * 2);
            aF[kt][1] = *(const uint32_t*)(hp8 + kt * 16 + tig * 2);
            aF[kt][2] = *(const uint32_t*)(hp0 + kt * 16 + tig * 2 + 8);
            aF[kt][3] = *(const uint32_t*)(hp8 + kt * 16 + tig * 2 + 8);
        }
    }

    // ldmatrix per-lane address components (swizzle folded in)
    const int la = lane >> 3;   // tile slot 0..3 within x4
    const int lb = lane & 7;    // row within tile
    uint32_t rq[4], xk[4];
#pragma unroll
    for (int q = 0; q < 4; q++)
        rq[q] = (uint32_t)(((2 * q + (la >> 1)) * 8 + lb) * 128);
#pragma unroll
    for (int kt = 0; kt < 4; kt++)
        xk[kt] = (uint32_t)((kt * 32 + (la & 1) * 16) ^ (lb << 4));

    // persistent contraction outputs: [row(2)][vslot(4)][comp(5: ps,t1,t2x,t2y,t2z)]
    float out[2][4][5];
#pragma unroll
    for (int a = 0; a < 2; a++)
#pragma unroll
        for (int s = 0; s < 4; s++)
#pragma unroll
            for (int q = 0; q < 5; q++) out[a][s][q] = 0.f;

    const int e0 = w * 16 + gid, e1 = e0 + 8;

    // ---------------- main loop: 16 chunks of 64 w2 columns ----------------
    // Invariant: at top of iteration c, every thread has finished reading
    // buffer (c+1)&1 (enforced by the end-of-iteration __syncthreads), so
    // tid0 may immediately issue chunk c+1 into it.
    for (int c = 0; c < 16; c++) {
        if (tid == 0 && c + 1 < 16) {
            const uint32_t mb = mb_u32 + ((c + 1) & 1) * 16;
            mb_expect_tx(mb, CHUNK_BYTES);
            bulk_cp(w2_u32 + ((c + 1) & 1) * CHUNK_BYTES,
                    g_w2s + (c + 1) * 4096, mb);
        }

        mb_wait(mb_u32 + (c & 1) * 16, (c >> 1) & 1);   // chunk c landed
        const uint32_t Bb = w2_u32 + (c & 1) * CHUNK_BYTES;

        // accumulators init = b2[j] (broadcast over rows)
        float acc[8][4];
#pragma unroll
        for (int t = 0; t < 8; t++) {
            float bz0 = s_b2[c * 64 + t * 8 + tig * 2];
            float bz1 = s_b2[c * 64 + t * 8 + tig * 2 + 1];
            acc[t][0] = bz0; acc[t][1] = bz1; acc[t][2] = bz0; acc[t][3] = bz1;
        }

#pragma unroll
        for (int kt = 0; kt < 4; kt++) {
            uint32_t bf[8][2];
#pragma unroll
            for (int q = 0; q < 4; q++) {
                uint32_t addr = Bb + rq[q] + xk[kt];
                asm volatile("ldmatrix.sync.aligned.m8n8.x4.shared.b16 "
                             "{%0,%1,%2,%3}, [%4];"
                             : "=r"(bf[2 * q][0]), "=r"(bf[2 * q][1]),
                               "=r"(bf[2 * q + 1][0]), "=r"(bf[2 * q + 1][1])
                             : "r"(addr));
            }
#pragma unroll
            for (int t = 0; t < 8; t++) {
                asm volatile(
                    "mma.sync.aligned.m16n8k16.row.col.f32.f16.f16.f32 "
                    "{%0,%1,%2,%3}, {%4,%5,%6,%7}, {%8,%9}, {%0,%1,%2,%3};"
                    : "+f"(acc[t][0]), "+f"(acc[t][1]), "+f"(acc[t][2]), "+f"(acc[t][3])
                    : "r"(aF[kt][0]), "r"(aF[kt][1]), "r"(aF[kt][2]), "r"(aF[kt][3]),
                      "r"(bf[t][0]), "r"(bf[t][1]));
            }
        }

        // ------------- epilogue: contract chunk into out regs -------------
        const int gq = c >> 2;            // which W block
        const int ub = (c & 3) * 4;       // u base for this chunk

#define EPI_ARM(COMP, OC)                                                     \
        {                                                                     \
            float4 c4a = *(const float4*)(s_co + e0 * 100 + (COMP) * 16 + ub);\
            float4 c4b = *(const float4*)(s_co + e1 * 100 + (COMP) * 16 + ub);\
            float cR0[4] = {c4a.x, c4a.y, c4a.z, c4a.w};                      \
            float cR1[4] = {c4b.x, c4b.y, c4b.z, c4b.w};                      \
            _Pragma("unroll")                                                 \
            for (int t = 0; t < 8; t++) {                                     \
                const int uu = t >> 1, sb = (t & 1) * 2;                      \
                out[0][sb    ][(OC)] += cR0[uu] * acc[t][0];                  \
                out[0][sb + 1][(OC)] += cR0[uu] * acc[t][1];                  \
                out[1][sb    ][(OC)] += cR1[uu] * acc[t][2];                  \
                out[1][sb + 1][(OC)] += cR1[uu] * acc[t][3];                  \
            }                                                                 \
        }

        if (gq == 0)      EPI_ARM(0, 0)       // W00: a_u -> ps
        else if (gq == 1) EPI_ARM(2, 1)       // W01: xs_u -> t1
        else if (gq == 3) EPI_ARM(1, 0)       // W11: b_u -> ps
        else {                                // W10: x_i*shs -> t2i
            EPI_ARM(3, 2)
            EPI_ARM(4, 3)
            EPI_ARM(5, 4)
        }
#undef EPI_ARM

        __syncthreads();   // all warps done reading buffer c&1 -> reissuable
    }

    // ---------------- scatter: atomic add into g_agg ----------------
    const float alpha = 0.17677669529f;   // 1/sqrt(2*MUL)
#pragma unroll
    for (int row = 0; row < 2; row++) {
        const int eloc = w * 16 + gid + row * 8;
        long long e = blockBase + eloc;
        if (e < E) {
            int dst = s_dst[eloc];
            float sv0 = s_sh4[eloc * 4 + 1];
            float sv1 = s_sh4[eloc * 4 + 2];
            float sv2 = s_sh4[eloc * 4 + 3];
            float* dp = g_agg + (long long)dst * 64;
#pragma unroll
            for (int s = 0; s < 4; s++) {
                const int v = (s >> 1) * 8 + tig * 2 + (s & 1);
                atomicAdd(dp + v, alpha * out[row][s][0]);
                atomicAdd(dp + 16 + v * 3 + 0, alpha * (out[row][s][1] * sv0 + out[row][s][2]));
                atomicAdd(dp + 16 + v * 3 + 1, alpha * (out[row][s][1] * sv1 + out[row][s][3]));
                atomicAdd(dp + 16 + v * 3 + 2, alpha * (out[row][s][1] * sv2 + out[row][s][4]));
            }
        }
    }
}

// --------------------------------------------------------------------------
__global__ void node_kernel(const float* __restrict__ nf,
                            const float* __restrict__ lw0,
                            const float* __restrict__ lw1,
                            float* __restrict__ out, int N)
{
    int idx = blockIdx.x * blockDim.x + threadIdx.x;
    int n = idx >> 4, v = idx & 15;
    if (n >= N) return;

    const float* ag = g_agg + (long long)n * 64;
    float ts = 0.f, tv0 = 0.f, tv1 = 0.f, tv2 = 0.f;
#pragma unroll
    for (int u = 0; u < 16; u++) {
        float l0 = __ldg(lw0 + u * 16 + v);
        float l1 = __ldg(lw1 + u * 16 + v);
        ts  += ag[u] * l0;
        tv0 += ag[16 + u * 3 + 0] * l1;
        tv1 += ag[16 + u * 3 + 1] * l1;
        tv2 += ag[16 + u * 3 + 2] * l1;
    }
    const float s = 0.25f;   // 1/sqrt(MUL)
    ts *= s; tv0 *= s; tv1 *= s; tv2 *= s;

    const float eps = 1e-8f;
    float ns = fabsf(ts);
    float gs = ns / ((1.f + expf(-ns)) * (ns + eps));
    float nv = sqrtf(tv0 * tv0 + tv1 * tv1 + tv2 * tv2);
    float gv = nv / ((1.f + expf(-nv)) * (nv + eps));

    const float* nfp = nf + (long long)n * 64;
    float*       op  = out + (long long)n * 64;
    op[v]              = nfp[v]              + ts  * gs;
    op[16 + v * 3 + 0] = nfp[16 + v * 3 + 0] + tv0 * gv;
    op[16 + v * 3 + 1] = nfp[16 + v * 3 + 1] + tv1 * gv;
    op[16 + v * 3 + 2] = nfp[16 + v * 3 + 2] + tv2 * gv;
}

// --------------------------------------------------------------------------
extern "C" void kernel_launch(void* const* d_in, const int* in_sizes, int n_in,
                              void* d_out, int out_size)
{
    const float* nf  = (const float*)d_in[0];   // node_features (N,64)
    const float* esh = (const float*)d_in[1];   // edge_sh (E,4)
    const float* emb = (const float*)d_in[2];   // edge_radial_emb (E,16)
    const float* w1  = (const float*)d_in[3];   // (16,64)
    const float* b1  = (const float*)d_in[4];   // (64)
    const float* w2  = (const float*)d_in[5];   // (64,1024)
    const float* b2  = (const float*)d_in[6];   // (1024)
    const float* lw0 = (const float*)d_in[7];   // (16,16)
    const float* lw1 = (const float*)d_in[8];   // (16,16)
    const int*   eix = (const int*)d_in[9];     // (2,E)

    int N = in_sizes[0] / 64;
    int E = in_sizes[2] / 16;
    float* out = (float*)d_out;

    cudaFuncSetAttribute(edge_kernel,
                         cudaFuncAttributeMaxDynamicSharedMemorySize, SMEM_BYTES);

    int n4 = N * 16;
    int prepN = (n4 > 65536) ? n4 : 65536;
    prep_kernel<<<(prepN + 255) / 256, 256>>>(w2, n4);
    edge_kernel<<<(E + 127) / 128, 256, SMEM_BYTES>>>(nf, esh, emb, w1, b1, b2, eix, E);
    node_kernel<<<(N * 16 + 255) / 256, 256>>>(nf, lw0, lw1, out, N);
}

// round 14
// speedup vs baseline: 9.4943x; 1.1197x over previous
#include <cuda_runtime.h>
#include <cuda_fp16.h>
#include <cstdint>

// ---------------------------------------------------------------------------
// TFN interaction block — fp16 mma.m16n8k16 + cp.async.bulk 4-stage ring.
//
//  prep_kernel: zero accumulators; build g_w2s = w2 as half, transposed [j][k],
//               chunk-contiguous (16 chunks x 8KB) with XOR-16B swizzle baked in.
//  edge_kernel: CTA = 256 thr / 8 warps = 128 edges, 2 CTAs/SM.
//               4-stage ring of 8KB w2 chunks, ONE cp.async.bulk per chunk.
//               Buffer recycling is guarded ONLY by the end-of-iteration
//               __syncthreads (chunk c+3 reuses the buffer last read in
//               iteration c-1) -> deterministic, no empty barriers, depth 3.
//               B fragments via ldmatrix.x4; per-chunk tpw contracted into 40
//               per-thread output registers; vectorized red.v2.f32 scatter.
//  node_kernel: per-node linear + gated SiLU + residual.
// ---------------------------------------------------------------------------

#define NMAX 10000

__device__ float  g_agg[NMAX * 64];   // [n][0:16]=agg_s, [n][16+u*3+i]=agg_v
__device__ __half g_w2s[16 * 4096];   // swizzled w2^T, chunk-contiguous

// --------------------------------------------------------------------------
__global__ void prep_kernel(const float* __restrict__ w2, int n4)
{
    int i = blockIdx.x * blockDim.x + threadIdx.x;
    if (i < n4) reinterpret_cast<float4*>(g_agg)[i] = make_float4(0.f, 0.f, 0.f, 0.f);
    if (i < 65536) {
        int k = i >> 10, j = i & 1023;        // coalesced read of w2[k][j]
        int c = j >> 6, r = j & 63;
        int idx = c * 4096 + r * 64 + (k ^ ((r & 7) * 8));   // 16B-granule XOR swizzle
        g_w2s[idx] = __float2half_rn(w2[i]);
    }
}

// --------------------------------------------------------------------------
// Shared memory layout (bytes). Total 113216 B -> 2 CTAs/SM.
#define OFF_W2   0         // 4 x 8192 = 32768  (4-stage w2 chunk ring, swizzled)
#define OFF_H    32768     // 128 x 72 halves = 18432
#define OFF_CO   51200     // 128 x 100 floats = 51200
#define OFF_W1   102400    // 4096
#define OFF_B2   106496    // 4096
#define OFF_SH4  110592    // 2048
#define OFF_DST  112640    // 512
#define OFF_MB   113152    // full[s] mbarrier @ +s*16
#define SMEM_BYTES 113216
#define CHUNK_BYTES 8192

__device__ __forceinline__ void mb_init(uint32_t a, uint32_t cnt) {
    asm volatile("mbarrier.init.shared.b64 [%0], %1;" :: "r"(a), "r"(cnt) : "memory");
}
__device__ __forceinline__ void mb_expect_tx(uint32_t a, uint32_t bytes) {
    asm volatile("mbarrier.arrive.expect_tx.shared.b64 _, [%0], %1;" :: "r"(a), "r"(bytes) : "memory");
}
__device__ __forceinline__ void mb_wait(uint32_t a, uint32_t parity) {
    uint32_t done;
    asm volatile("{\n\t.reg .pred p;\n\t"
                 "mbarrier.try_wait.parity.acquire.cta.shared::cta.b64 p, [%1], %2;\n\t"
                 "selp.b32 %0, 1, 0, p;\n\t}"
                 : "=r"(done) : "r"(a), "r"(parity) : "memory");
    if (!done) {
        asm volatile("{\n\t.reg .pred P1;\n\t"
                     "W_%=:\n\t"
                     "mbarrier.try_wait.parity.acquire.cta.shared::cta.b64 P1, [%0], %1, 0x989680;\n\t"
                     "@P1 bra.uni D_%=;\n\t"
                     "bra.uni W_%=;\n\t"
                     "D_%=:\n\t}"
                     :: "r"(a), "r"(parity) : "memory");
    }
}
__device__ __forceinline__ void bulk_cp(uint32_t dst, const void* src, uint32_t mbar) {
    asm volatile("cp.async.bulk.shared::cta.global.mbarrier::complete_tx::bytes "
                 "[%0], [%1], %2, [%3];"
                 :: "r"(dst), "l"(src), "r"((uint32_t)CHUNK_BYTES), "r"(mbar) : "memory");
}
__device__ __forceinline__ void red2(float* p, float a, float b) {
    asm volatile("red.global.add.v2.f32 [%0], {%1, %2};"
                 :: "l"(p), "f"(a), "f"(b) : "memory");
}

// --------------------------------------------------------------------------
__global__ __launch_bounds__(256, 2)
void edge_kernel(const float* __restrict__ nf,  const float* __restrict__ esh,
                 const float* __restrict__ emb, const float* __restrict__ w1,
                 const float* __restrict__ b1,  const float* __restrict__ b2,
                 const int*   __restrict__ eidx, int E)
{
    extern __shared__ __align__(16) char smem_raw[];
    __half* s_h   = (__half*)(smem_raw + OFF_H);
    float*  s_co  = (float*)(smem_raw + OFF_CO);
    float*  s_w1  = (float*)(smem_raw + OFF_W1);
    float*  s_b2  = (float*)(smem_raw + OFF_B2);
    float*  s_sh4 = (float*)(smem_raw + OFF_SH4);
    int*    s_dst = (int*)(smem_raw + OFF_DST);

    const uint32_t smem_u32 = (uint32_t)__cvta_generic_to_shared(smem_raw);
    const uint32_t w2_u32   = smem_u32 + OFF_W2;
    const uint32_t mb_u32   = smem_u32 + OFF_MB;

    const int tid  = threadIdx.x;
    const int w    = tid >> 5;
    const int lane = tid & 31;
    const int gid  = lane >> 2;   // 0..7
    const int tig  = lane & 3;    // 0..3

    // stage w1 + b2 (one float4 each per thread)
    reinterpret_cast<float4*>(s_w1)[tid] = reinterpret_cast<const float4*>(w1)[tid];
    reinterpret_cast<float4*>(s_b2)[tid] = reinterpret_cast<const float4*>(b2)[tid];

    if (tid == 0) {
#pragma unroll
        for (int s = 0; s < 4; s++) mb_init(mb_u32 + s * 16, 1);
    }
    __syncthreads();   // mbarriers + s_w1 visible

    // kick off chunks 0..2 (overlap the prologue); ring has 4 buffers.
    if (tid == 0) {
#pragma unroll
        for (int q = 0; q < 3; q++) {
            mb_expect_tx(mb_u32 + q * 16, CHUNK_BYTES);
            bulk_cp(w2_u32 + q * CHUNK_BYTES, g_w2s + q * 4096, mb_u32 + q * 16);
        }
    }

    // ---------------- prologue: per-warp 16 edges ----------------
    const long long blockBase = (long long)blockIdx.x * 128;
    const float inv3 = 0.57735026919f;

    for (int r = 0; r < 16; r++) {
        const int eloc = w * 16 + r;
        long long e = blockBase + eloc;
        bool ok = (e < E);
        long long ec = ok ? e : 0;
        int src = eidx[ec];
        if (lane == 0) s_dst[eloc] = eidx[E + ec];

        // h = silu(emb @ w1 + b1) -> half
        float embv = (lane < 16 && ok) ? emb[ec * 16 + lane] : 0.f;
        float h0 = b1[lane], h1 = b1[lane + 32];
#pragma unroll
        for (int nb = 0; nb < 16; nb++) {
            float ev = __shfl_sync(0xffffffffu, embv, nb);
            h0 += ev * s_w1[nb * 64 + lane];
            h1 += ev * s_w1[nb * 64 + lane + 32];
        }
        h0 = h0 / (1.f + expf(-h0));
        h1 = h1 / (1.f + expf(-h1));
        if (!ok) { h0 = 0.f; h1 = 0.f; }
        s_h[eloc * 72 + lane]      = __float2half_rn(h0);
        s_h[eloc * 72 + lane + 32] = __float2half_rn(h1);

        // coefficients (lane u < 16); layout [e][comp*16+u], edge stride 100
        if (lane < 16) {
            int u = lane;
            const float* nfp = nf + (long long)src * 64;
            float xs = nfp[u];
            float x0 = nfp[16 + u * 3 + 0];
            float x1 = nfp[16 + u * 3 + 1];
            float x2 = nfp[16 + u * 3 + 2];
            float shs = esh[ec * 4 + 0], sv0 = esh[ec * 4 + 1];
            float sv1 = esh[ec * 4 + 2], sv2 = esh[ec * 4 + 3];
            if (!ok) { xs = x0 = x1 = x2 = 0.f; shs = sv0 = sv1 = sv2 = 0.f; }
            float* cp = s_co + eloc * 100;
            cp[0 * 16 + u] = xs * shs;                                  // a_u  (W00 -> ps)
            cp[1 * 16 + u] = inv3 * (x0 * sv0 + x1 * sv1 + x2 * sv2);   // b_u  (W11 -> ps)
            cp[2 * 16 + u] = xs;                                        // W01 -> t1
            cp[3 * 16 + u] = x0 * shs;                                  // W10 -> t2x
            cp[4 * 16 + u] = x1 * shs;                                  // W10 -> t2y
            cp[5 * 16 + u] = x2 * shs;                                  // W10 -> t2z
            if (u == 0) {
                s_sh4[eloc * 4 + 0] = shs; s_sh4[eloc * 4 + 1] = sv0;
                s_sh4[eloc * 4 + 2] = sv1; s_sh4[eloc * 4 + 3] = sv2;
            }
        }
    }
    __syncthreads();   // s_h / s_co / s_dst / s_sh4 visible

    // A fragments (m16n8k16): rows gid, gid+8; k pairs packed as u32
    uint32_t aF[4][4];
    {
        const __half* hp0 = s_h + (w * 16 + gid) * 72;
        const __half* hp8 = s_h + (w * 16 + gid + 8) * 72;
#pragma unroll
        for (int kt = 0; kt < 4; kt++) {
            aF[kt][0] = *(const uint32_t*)(hp0 + kt * 16 + tig * 2);
            aF[kt][1] = *(const uint32_t*)(hp8 + kt * 16 + tig * 2);
            aF[kt][2] = *(const uint32_t*)(hp0 + kt * 16 + tig * 2 + 8);
            aF[kt][3] = *(const uint32_t*)(hp8 + kt * 16 + tig * 2 + 8);
        }
    }

    // ldmatrix per-lane address components (swizzle folded in)
    const int la = lane >> 3;   // tile slot 0..3 within x4
    const int lb = lane & 7;    // row within tile
    uint32_t rq[4], xk[4];
#pragma unroll
    for (int q = 0; q < 4; q++)
        rq[q] = (uint32_t)(((2 * q + (la >> 1)) * 8 + lb) * 128);
#pragma unroll
    for (int kt = 0; kt < 4; kt++)
        xk[kt] = (uint32_t)((kt * 32 + (la & 1) * 16) ^ (lb << 4));

    // persistent contraction outputs: [row(2)][vslot(4)][comp(5: ps,t1,t2x,t2y,t2z)]
    float out[2][4][5];
#pragma unroll
    for (int a = 0; a < 2; a++)
#pragma unroll
        for (int s = 0; s < 4; s++)
#pragma unroll
            for (int q = 0; q < 5; q++) out[a][s][q] = 0.f;

    const int e0 = w * 16 + gid, e1 = e0 + 8;

    // ---------------- main loop: 16 chunks of 64 w2 columns ----------------
    // Ring invariant: chunk c+3 writes buffer (c+3)&3 == (c-1)&3, whose last
    // readers finished before the __syncthreads ending iteration c-1.
    for (int c = 0; c < 16; c++) {
        if (tid == 0 && c + 3 < 16) {
            const int q = c + 3;
            const uint32_t mb = mb_u32 + (q & 3) * 16;
            mb_expect_tx(mb, CHUNK_BYTES);
            bulk_cp(w2_u32 + (q & 3) * CHUNK_BYTES, g_w2s + q * 4096, mb);
        }

        // accumulators init = b2[j] (independent of the chunk buffer)
        float acc[8][4];
#pragma unroll
        for (int t = 0; t < 8; t++) {
            float bz0 = s_b2[c * 64 + t * 8 + tig * 2];
            float bz1 = s_b2[c * 64 + t * 8 + tig * 2 + 1];
            acc[t][0] = bz0; acc[t][1] = bz1; acc[t][2] = bz0; acc[t][3] = bz1;
        }

        mb_wait(mb_u32 + (c & 3) * 16, (c >> 2) & 1);   // chunk c landed
        const uint32_t Bb = w2_u32 + (c & 3) * CHUNK_BYTES;

#pragma unroll
        for (int kt = 0; kt < 4; kt++) {
            uint32_t bf[8][2];
#pragma unroll
            for (int q = 0; q < 4; q++) {
                uint32_t addr = Bb + rq[q] + xk[kt];
                asm volatile("ldmatrix.sync.aligned.m8n8.x4.shared.b16 "
                             "{%0,%1,%2,%3}, [%4];"
                             : "=r"(bf[2 * q][0]), "=r"(bf[2 * q][1]),
                               "=r"(bf[2 * q + 1][0]), "=r"(bf[2 * q + 1][1])
                             : "r"(addr));
            }
#pragma unroll
            for (int t = 0; t < 8; t++) {
                asm volatile(
                    "mma.sync.aligned.m16n8k16.row.col.f32.f16.f16.f32 "
                    "{%0,%1,%2,%3}, {%4,%5,%6,%7}, {%8,%9}, {%0,%1,%2,%3};"
                    : "+f"(acc[t][0]), "+f"(acc[t][1]), "+f"(acc[t][2]), "+f"(acc[t][3])
                    : "r"(aF[kt][0]), "r"(aF[kt][1]), "r"(aF[kt][2]), "r"(aF[kt][3]),
                      "r"(bf[t][0]), "r"(bf[t][1]));
            }
        }

        // ------------- epilogue: contract chunk into out regs -------------
        const int gq = c >> 2;            // which W block
        const int ub = (c & 3) * 4;       // u base for this chunk

#define EPI_ARM(COMP, OC)                                                     \
        {                                                                     \
            float4 c4a = *(const float4*)(s_co + e0 * 100 + (COMP) * 16 + ub);\
            float4 c4b = *(const float4*)(s_co + e1 * 100 + (COMP) * 16 + ub);\
            float cR0[4] = {c4a.x, c4a.y, c4a.z, c4a.w};                      \
            float cR1[4] = {c4b.x, c4b.y, c4b.z, c4b.w};                      \
            _Pragma("unroll")                                                 \
            for (int t = 0; t < 8; t++) {                                     \
                const int uu = t >> 1, sb = (t & 1) * 2;                      \
                out[0][sb    ][(OC)] += cR0[uu] * acc[t][0];                  \
                out[0][sb + 1][(OC)] += cR0[uu] * acc[t][1];                  \
                out[1][sb    ][(OC)] += cR1[uu] * acc[t][2];                  \
                out[1][sb + 1][(OC)] += cR1[uu] * acc[t][3];                  \
            }                                                                 \
        }

        if (gq == 0)      EPI_ARM(0, 0)       // W00: a_u -> ps
        else if (gq == 1) EPI_ARM(2, 1)       // W01: xs_u -> t1
        else if (gq == 3) EPI_ARM(1, 0)       // W11: b_u -> ps
        else {                                // W10: x_i*shs -> t2i
            EPI_ARM(3, 2)
            EPI_ARM(4, 3)
            EPI_ARM(5, 4)
        }
#undef EPI_ARM

        __syncthreads();   // all warps done reading buffer c&3 -> reissuable
    }

    // ---------------- scatter: vectorized red.add.v2.f32 into g_agg ----------------
    const float alpha = 0.17677669529f;   // 1/sqrt(2*MUL)
#pragma unroll
    for (int row = 0; row < 2; row++) {
        const int eloc = w * 16 + gid + row * 8;
        long long e = blockBase + eloc;
        if (e < E) {
            int dst = s_dst[eloc];
            float sv0 = s_sh4[eloc * 4 + 1];
            float sv1 = s_sh4[eloc * 4 + 2];
            float sv2 = s_sh4[eloc * 4 + 3];
            float* dp = g_agg + (long long)dst * 64;
#pragma unroll
            for (int p = 0; p < 2; p++) {          // slot pairs (0,1) and (2,3)
                const int sa = p * 2, sb = sa + 1;
                const int vb = p * 8 + tig * 2;    // v base (even)
                // scalar part: v = vb, vb+1
                red2(dp + vb, alpha * out[row][sa][0], alpha * out[row][sb][0]);
                // vector part: 6 consecutive floats at dp+16+3*vb
                float xa = alpha * (out[row][sa][1] * sv0 + out[row][sa][2]);
                float ya = alpha * (out[row][sa][1] * sv1 + out[row][sa][3]);
                float za = alpha * (out[row][sa][1] * sv2 + out[row][sa][4]);
                float xb = alpha * (out[row][sb][1] * sv0 + out[row][sb][2]);
                float yb = alpha * (out[row][sb][1] * sv1 + out[row][sb][3]);
                float zb = alpha * (out[row][sb][1] * sv2 + out[row][sb][4]);
                float* vp = dp + 16 + 3 * vb;
                red2(vp,     xa, ya);
                red2(vp + 2, za, xb);
                red2(vp + 4, yb, zb);
            }
        }
    }
}

// --------------------------------------------------------------------------
__global__ void node_kernel(const float* __restrict__ nf,
                            const float* __restrict__ lw0,
                            const float* __restrict__ lw1,
                            float* __restrict__ out, int N)
{
    int idx = blockIdx.x * blockDim.x + threadIdx.x;
    int n = idx >> 4, v = idx & 15;
    if (n >= N) return;

    const float* ag = g_agg + (long long)n * 64;
    float ts = 0.f, tv0 = 0.f, tv1 = 0.f, tv2 = 0.f;
#pragma unroll
    for (int u = 0; u < 16; u++) {
        float l0 = __ldg(lw0 + u * 16 + v);
        float l1 = __ldg(lw1 + u * 16 + v);
        ts  += ag[u] * l0;
        tv0 += ag[16 + u * 3 + 0] * l1;
        tv1 += ag[16 + u * 3 + 1] * l1;
        tv2 += ag[16 + u * 3 + 2] * l1;
    }
    const float s = 0.25f;   // 1/sqrt(MUL)
    ts *= s; tv0 *= s; tv1 *= s; tv2 *= s;

    const float eps = 1e-8f;
    float ns = fabsf(ts);
    float gs = ns / ((1.f + expf(-ns)) * (ns + eps));
    float nv = sqrtf(tv0 * tv0 + tv1 * tv1 + tv2 * tv2);
    float gv = nv / ((1.f + expf(-nv)) * (nv + eps));

    const float* nfp = nf + (long long)n * 64;
    float*       op  = out + (long long)n * 64;
    op[v]              = nfp[v]              + ts  * gs;
    op[16 + v * 3 + 0] = nfp[16 + v * 3 + 0] + tv0 * gv;
    op[16 + v * 3 + 1] = nfp[16 + v * 3 + 1] + tv1 * gv;
    op[16 + v * 3 + 2] = nfp[16 + v * 3 + 2] + tv2 * gv;
}

// --------------------------------------------------------------------------
extern "C" void kernel_launch(void* const* d_in, const int* in_sizes, int n_in,
                              void* d_out, int out_size)
{
    const float* nf  = (const float*)d_in[0];   // node_features (N,64)
    const float* esh = (const float*)d_in[1];   // edge_sh (E,4)
    const float* emb = (const float*)d_in[2];   // edge_radial_emb (E,16)
    const float* w1  = (const float*)d_in[3];   // (16,64)
    const float* b1  = (const float*)d_in[4];   // (64)
    const float* w2  = (const float*)d_in[5];   // (64,1024)
    const float* b2  = (const float*)d_in[6];   // (1024)
    const float* lw0 = (const float*)d_in[7];   // (16,16)
    const float* lw1 = (const float*)d_in[8];   // (16,16)
    const int*   eix = (const int*)d_in[9];     // (2,E)

    int N = in_sizes[0] / 64;
    int E = in_sizes[2] / 16;
    float* out = (float*)d_out;

    cudaFuncSetAttribute(edge_kernel,
                         cudaFuncAttributeMaxDynamicSharedMemorySize, SMEM_BYTES);

    int n4 = N * 16;
    int prepN = (n4 > 65536) ? n4 : 65536;
    prep_kernel<<<(prepN + 255) / 256, 256>>>(w2, n4);
    edge_kernel<<<(E + 127) / 128, 256, SMEM_BYTES>>>(nf, esh, emb, w1, b1, b2, eix, E);
    node_kernel<<<(N * 16 + 255) / 256, 256>>>(nf, lw0, lw1, out, N);
}

// round 17
// speedup vs baseline: 12.7019x; 1.3378x over previous
#include <cuda_runtime.h>
#include <cuda_fp16.h>
#include <cstdint>

// ---------------------------------------------------------------------------
// TFN interaction block — fp16 mma.m16n8k16, fully tensorized prologue.
//
//  prep_kernel: zero accumulators; g_w2s = w2 half [j][k] chunk-contiguous
//               with XOR-16B swizzle; g_w1th = w1 half transposed [j][nb].
//  edge_kernel: CTA = 256 thr / 8 warps = 128 edges, 2 CTAs/SM.
//               Prologue: h = silu(emb@w1+b1) via 8 MMAs, output fragments
//               become the A fragments of the main GEMM (register-to-register,
//               no smem h). Coefficients built in 8 warp-wide iterations.
//               Main loop: 4-stage cp.async.bulk ring, chunk PAIRS between
//               __syncthreads (8 syncs), issue c+4/c+5 post-sync. ldmatrix.x4
//               B fragments; per-chunk contraction into 40 output registers;
//               vectorized red.v2.f32 scatter.
//  node_kernel: per-node linear + gated SiLU + residual.
// ---------------------------------------------------------------------------

#define NMAX 10000

__device__ float  g_agg[NMAX * 64];   // [n][0:16]=agg_s, [n][16+u*3+i]=agg_v
__device__ __half g_w2s[16 * 4096];   // swizzled w2^T, chunk-contiguous
__device__ __half g_w1th[64 * 16];    // w1 transposed [j][nb], half

// --------------------------------------------------------------------------
__global__ void prep_kernel(const float* __restrict__ w2,
                            const float* __restrict__ w1, int n4)
{
    int i = blockIdx.x * blockDim.x + threadIdx.x;
    if (i < n4) reinterpret_cast<float4*>(g_agg)[i] = make_float4(0.f, 0.f, 0.f, 0.f);
    if (i < 65536) {
        int k = i >> 10, j = i & 1023;        // coalesced read of w2[k][j]
        int c = j >> 6, r = j & 63;
        int idx = c * 4096 + r * 64 + (k ^ ((r & 7) * 8));   // 16B-granule XOR swizzle
        g_w2s[idx] = __float2half_rn(w2[i]);
    }
    if (i < 1024) {
        int nb = i >> 6, j = i & 63;
        g_w1th[j * 16 + nb] = __float2half_rn(w1[i]);
    }
}

// --------------------------------------------------------------------------
// Shared memory layout (bytes). Total 92992 B -> 2 CTAs/SM.
#define OFF_W2   0         // 4 x 8192 = 32768  (4-stage w2 chunk ring, swizzled)
#define OFF_CO   32768     // 128 x 100 floats = 51200  (coeffs [e][comp*16+u])
#define OFF_B2   83968     // 4096
#define OFF_SH4  88064     // 2048
#define OFF_DST  90112     // 512
#define OFF_MB   90624     // full[s] mbarrier @ +s*16
#define SMEM_BYTES 90688
#define CHUNK_BYTES 8192

__device__ __forceinline__ void mb_init(uint32_t a, uint32_t cnt) {
    asm volatile("mbarrier.init.shared.b64 [%0], %1;" :: "r"(a), "r"(cnt) : "memory");
}
__device__ __forceinline__ void mb_expect_tx(uint32_t a, uint32_t bytes) {
    asm volatile("mbarrier.arrive.expect_tx.shared.b64 _, [%0], %1;" :: "r"(a), "r"(bytes) : "memory");
}
__device__ __forceinline__ void mb_wait(uint32_t a, uint32_t parity) {
    uint32_t done;
    asm volatile("{\n\t.reg .pred p;\n\t"
                 "mbarrier.try_wait.parity.acquire.cta.shared::cta.b64 p, [%1], %2;\n\t"
                 "selp.b32 %0, 1, 0, p;\n\t}"
                 : "=r"(done) : "r"(a), "r"(parity) : "memory");
    if (!done) {
        asm volatile("{\n\t.reg .pred P1;\n\t"
                     "W_%=:\n\t"
                     "mbarrier.try_wait.parity.acquire.cta.shared::cta.b64 P1, [%0], %1, 0x989680;\n\t"
                     "@P1 bra.uni D_%=;\n\t"
                     "bra.uni W_%=;\n\t"
                     "D_%=:\n\t}"
                     :: "r"(a), "r"(parity) : "memory");
    }
}
__device__ __forceinline__ void bulk_cp(uint32_t dst, const void* src, uint32_t mbar) {
    asm volatile("cp.async.bulk.shared::cta.global.mbarrier::complete_tx::bytes "
                 "[%0], [%1], %2, [%3];"
                 :: "r"(dst), "l"(src), "r"((uint32_t)CHUNK_BYTES), "r"(mbar) : "memory");
}
__device__ __forceinline__ void red2(float* p, float a, float b) {
    asm volatile("red.global.add.v2.f32 [%0], {%1, %2};"
                 :: "l"(p), "f"(a), "f"(b) : "memory");
}
__device__ __forceinline__ uint32_t packh2(float a, float b) {
    __half2 h = __floats2half2_rn(a, b);
    return *reinterpret_cast<uint32_t*>(&h);
}
__device__ __forceinline__ float silu_f(float v) {
    return v / (1.f + __expf(-v));
}

// --------------------------------------------------------------------------
__global__ __launch_bounds__(256, 2)
void edge_kernel(const float* __restrict__ nf,  const float* __restrict__ esh,
                 const float* __restrict__ emb, const float* __restrict__ b1,
                 const float* __restrict__ b2,  const int*   __restrict__ eidx,
                 int E)
{
    extern __shared__ __align__(16) char smem_raw[];
    float*  s_co  = (float*)(smem_raw + OFF_CO);
    float*  s_b2  = (float*)(smem_raw + OFF_B2);
    float*  s_sh4 = (float*)(smem_raw + OFF_SH4);
    int*    s_dst = (int*)(smem_raw + OFF_DST);

    const uint32_t smem_u32 = (uint32_t)__cvta_generic_to_shared(smem_raw);
    const uint32_t w2_u32   = smem_u32 + OFF_W2;
    const uint32_t mb_u32   = smem_u32 + OFF_MB;

    const int tid  = threadIdx.x;
    const int w    = tid >> 5;
    const int lane = tid & 31;
    const int gid  = lane >> 2;   // 0..7
    const int tig  = lane & 3;    // 0..3

    // stage b2 (one float4 per thread)
    reinterpret_cast<float4*>(s_b2)[tid] = reinterpret_cast<const float4*>(b2)[tid];

    if (tid == 0) {
#pragma unroll
        for (int s = 0; s < 4; s++) mb_init(mb_u32 + s * 16, 1);
    }
    __syncthreads();   // mbarriers + s_b2 visible

    // kick off chunks 0..3 (all 4 ring buffers free)
    if (tid == 0) {
#pragma unroll
        for (int q = 0; q < 4; q++) {
            mb_expect_tx(mb_u32 + q * 16, CHUNK_BYTES);
            bulk_cp(w2_u32 + q * CHUNK_BYTES, g_w2s + q * 4096, mb_u32 + q * 16);
        }
    }

    const long long blockBase = (long long)blockIdx.x * 128;
    const float inv3 = 0.57735026919f;

    // ---------------- prologue A: h = silu(emb @ w1 + b1) via MMA ----------
    // A fragments (emb, fp32->fp16) straight from gmem.
    uint32_t aF[4][4];
    {
        long long eA0 = blockBase + w * 16 + gid;
        long long eA1 = eA0 + 8;
        const float* ep0 = emb + (eA0 < E ? eA0 : 0) * 16;
        const float* ep1 = emb + (eA1 < E ? eA1 : 0) * 16;
        uint32_t aE[4];
        float2 p;
        p = *(const float2*)(ep0 + tig * 2);     aE[0] = packh2(p.x, p.y);
        p = *(const float2*)(ep1 + tig * 2);     aE[1] = packh2(p.x, p.y);
        p = *(const float2*)(ep0 + tig * 2 + 8); aE[2] = packh2(p.x, p.y);
        p = *(const float2*)(ep1 + tig * 2 + 8); aE[3] = packh2(p.x, p.y);

        float hacc[8][4];
#pragma unroll
        for (int t = 0; t < 8; t++) {
            float b0 = b1[t * 8 + tig * 2];
            float b1v = b1[t * 8 + tig * 2 + 1];
            hacc[t][0] = b0; hacc[t][1] = b1v; hacc[t][2] = b0; hacc[t][3] = b1v;
        }
#pragma unroll
        for (int t = 0; t < 8; t++) {
            const __half* wp = g_w1th + (t * 8 + gid) * 16 + tig * 2;
            uint32_t wb0 = *(const uint32_t*)(wp);
            uint32_t wb1 = *(const uint32_t*)(wp + 8);
            asm volatile(
                "mma.sync.aligned.m16n8k16.row.col.f32.f16.f16.f32 "
                "{%0,%1,%2,%3}, {%4,%5,%6,%7}, {%8,%9}, {%0,%1,%2,%3};"
                : "+f"(hacc[t][0]), "+f"(hacc[t][1]), "+f"(hacc[t][2]), "+f"(hacc[t][3])
                : "r"(aE[0]), "r"(aE[1]), "r"(aE[2]), "r"(aE[3]),
                  "r"(wb0), "r"(wb1));
        }
        // silu + pack: h-MMA output fragment == main-GEMM A fragment (t = 2kt+tt)
#pragma unroll
        for (int kt = 0; kt < 4; kt++) {
#pragma unroll
            for (int tt = 0; tt < 2; tt++) {
                const int t = 2 * kt + tt;
                float s0 = silu_f(hacc[t][0]);
                float s1 = silu_f(hacc[t][1]);
                float s2 = silu_f(hacc[t][2]);
                float s3 = silu_f(hacc[t][3]);
                aF[kt][tt * 2 + 0] = packh2(s0, s1);
                aF[kt][tt * 2 + 1] = packh2(s2, s3);
            }
        }
    }

    // ---------------- prologue B: coefficients, 2 edges / iteration --------
    for (int r8 = 0; r8 < 8; r8++) {
        const int u    = lane & 15;
        const int eloc = w * 16 + r8 * 2 + (lane >> 4);
        long long e = blockBase + eloc;
        bool ok = (e < E);
        long long ec = ok ? e : 0;
        int srcv = 0;
        if (u == 0) srcv = eidx[ec];
        int src = __shfl_sync(0xffffffffu, srcv, lane & 16);
        if (u == 1) s_dst[eloc] = eidx[E + ec];
        float4 sh4 = *(const float4*)(esh + ec * 4);
        if (!ok) sh4 = make_float4(0.f, 0.f, 0.f, 0.f);
        const float* nfp = nf + (long long)src * 64;
        float xs = nfp[u];
        float x0 = nfp[16 + 3 * u], x1 = nfp[17 + 3 * u], x2 = nfp[18 + 3 * u];
        if (!ok) { xs = x0 = x1 = x2 = 0.f; }
        float* cp = s_co + eloc * 100;
        cp[u]      = xs * sh4.x;                                      // a_u (W00)
        cp[16 + u] = inv3 * (x0 * sh4.y + x1 * sh4.z + x2 * sh4.w);   // b_u (W11)
        cp[32 + u] = xs;                                              // W01 -> t1
        cp[48 + u] = x0 * sh4.x;                                      // W10 -> t2x
        cp[64 + u] = x1 * sh4.x;                                      // W10 -> t2y
        cp[80 + u] = x2 * sh4.x;                                      // W10 -> t2z
        if (u < 4) s_sh4[eloc * 4 + u] = (&sh4.x)[u];
    }
    __syncwarp();   // s_co / s_dst / s_sh4 are warp-local: warp sync suffices

    // ldmatrix per-lane address components (swizzle folded in)
    const int la = lane >> 3;   // tile slot 0..3 within x4
    const int lb = lane & 7;    // row within tile
    uint32_t rq[4], xk[4];
#pragma unroll
    for (int q = 0; q < 4; q++)
        rq[q] = (uint32_t)(((2 * q + (la >> 1)) * 8 + lb) * 128);
#pragma unroll
    for (int kt = 0; kt < 4; kt++)
        xk[kt] = (uint32_t)((kt * 32 + (la & 1) * 16) ^ (lb << 4));

    // persistent contraction outputs: [row(2)][vslot(4)][comp(5: ps,t1,t2x,t2y,t2z)]
    float out[2][4][5];
#pragma unroll
    for (int a = 0; a < 2; a++)
#pragma unroll
        for (int s = 0; s < 4; s++)
#pragma unroll
            for (int q = 0; q < 5; q++) out[a][s][q] = 0.f;

    const int e0 = w * 16 + gid, e1 = e0 + 8;

    // ---------------- main loop: 16 chunks, processed in pairs -------------
    // One __syncthreads per pair; afterwards issue chunks c2+4, c2+5 into
    // buffers (c2)&3, (c2+1)&3 whose readers just completed.
    for (int c2 = 0; c2 < 16; c2 += 2) {
#pragma unroll
        for (int ci = 0; ci < 2; ci++) {
            const int c = c2 + ci;

            // accumulators init = b2[j] (independent of the chunk buffer)
            float acc[8][4];
#pragma unroll
            for (int t = 0; t < 8; t++) {
                float bz0 = s_b2[c * 64 + t * 8 + tig * 2];
                float bz1 = s_b2[c * 64 + t * 8 + tig * 2 + 1];
                acc[t][0] = bz0; acc[t][1] = bz1; acc[t][2] = bz0; acc[t][3] = bz1;
            }

            mb_wait(mb_u32 + (c & 3) * 16, (c >> 2) & 1);   // chunk c landed
            const uint32_t Bb = w2_u32 + (c & 3) * CHUNK_BYTES;

#pragma unroll
            for (int kt = 0; kt < 4; kt++) {
                uint32_t bf[8][2];
#pragma unroll
                for (int q = 0; q < 4; q++) {
                    uint32_t addr = Bb + rq[q] + xk[kt];
                    asm volatile("ldmatrix.sync.aligned.m8n8.x4.shared.b16 "
                                 "{%0,%1,%2,%3}, [%4];"
                                 : "=r"(bf[2 * q][0]), "=r"(bf[2 * q][1]),
                                   "=r"(bf[2 * q + 1][0]), "=r"(bf[2 * q + 1][1])
                                 : "r"(addr));
                }
#pragma unroll
                for (int t = 0; t < 8; t++) {
                    asm volatile(
                        "mma.sync.aligned.m16n8k16.row.col.f32.f16.f16.f32 "
                        "{%0,%1,%2,%3}, {%4,%5,%6,%7}, {%8,%9}, {%0,%1,%2,%3};"
                        : "+f"(acc[t][0]), "+f"(acc[t][1]), "+f"(acc[t][2]), "+f"(acc[t][3])
                        : "r"(aF[kt][0]), "r"(aF[kt][1]), "r"(aF[kt][2]), "r"(aF[kt][3]),
                          "r"(bf[t][0]), "r"(bf[t][1]));
                }
            }

            // ------------- epilogue: contract chunk into out regs ---------
            const int gq = c >> 2;            // which W block
            const int ub = (c & 3) * 4;       // u base for this chunk

#define EPI_ARM(COMP, OC)                                                     \
            {                                                                 \
                float4 c4a = *(const float4*)(s_co + e0 * 100 + (COMP) * 16 + ub);\
                float4 c4b = *(const float4*)(s_co + e1 * 100 + (COMP) * 16 + ub);\
                float cR0[4] = {c4a.x, c4a.y, c4a.z, c4a.w};                  \
                float cR1[4] = {c4b.x, c4b.y, c4b.z, c4b.w};                  \
                _Pragma("unroll")                                             \
                for (int t = 0; t < 8; t++) {                                 \
                    const int uu = t >> 1, sb = (t & 1) * 2;                  \
                    out[0][sb    ][(OC)] += cR0[uu] * acc[t][0];              \
                    out[0][sb + 1][(OC)] += cR0[uu] * acc[t][1];              \
                    out[1][sb    ][(OC)] += cR1[uu] * acc[t][2];              \
                    out[1][sb + 1][(OC)] += cR1[uu] * acc[t][3];              \
                }                                                             \
            }

            if (gq == 0)      EPI_ARM(0, 0)       // W00: a_u -> ps
            else if (gq == 1) EPI_ARM(2, 1)       // W01: xs_u -> t1
            else if (gq == 3) EPI_ARM(1, 0)       // W11: b_u -> ps
            else {                                // W10: x_i*shs -> t2i
                EPI_ARM(3, 2)
                EPI_ARM(4, 3)
                EPI_ARM(5, 4)
            }
#undef EPI_ARM
        }

        __syncthreads();   // all warps done with buffers c2&3, (c2+1)&3
        if (tid == 0) {
#pragma unroll
            for (int d = 4; d < 6; d++) {
                const int q = c2 + d;
                if (q < 16) {
                    const uint32_t mb = mb_u32 + (q & 3) * 16;
                    mb_expect_tx(mb, CHUNK_BYTES);
                    bulk_cp(w2_u32 + (q & 3) * CHUNK_BYTES, g_w2s + q * 4096, mb);
                }
            }
        }
    }

    // ---------------- scatter: vectorized red.add.v2.f32 into g_agg --------
    const float alpha = 0.17677669529f;   // 1/sqrt(2*MUL)
#pragma unroll
    for (int row = 0; row < 2; row++) {
        const int eloc = w * 16 + gid + row * 8;
        long long e = blockBase + eloc;
        if (e < E) {
            int dst = s_dst[eloc];
            float sv0 = s_sh4[eloc * 4 + 1];
            float sv1 = s_sh4[eloc * 4 + 2];
            float sv2 = s_sh4[eloc * 4 + 3];
            float* dp = g_agg + (long long)dst * 64;
#pragma unroll
            for (int p = 0; p < 2; p++) {          // slot pairs (0,1) and (2,3)
                const int sa = p * 2, sb = sa + 1;
                const int vb = p * 8 + tig * 2;    // v base (even)
                red2(dp + vb, alpha * out[row][sa][0], alpha * out[row][sb][0]);
                float xa = alpha * (out[row][sa][1] * sv0 + out[row][sa][2]);
                float ya = alpha * (out[row][sa][1] * sv1 + out[row][sa][3]);
                float za = alpha * (out[row][sa][1] * sv2 + out[row][sa][4]);
                float xb = alpha * (out[row][sb][1] * sv0 + out[row][sb][2]);
                float yb = alpha * (out[row][sb][1] * sv1 + out[row][sb][3]);
                float zb = alpha * (out[row][sb][1] * sv2 + out[row][sb][4]);
                float* vp = dp + 16 + 3 * vb;
                red2(vp,     xa, ya);
                red2(vp + 2, za, xb);
                red2(vp + 4, yb, zb);
            }
        }
    }
}

// --------------------------------------------------------------------------
__global__ void node_kernel(const float* __restrict__ nf,
                            const float* __restrict__ lw0,
                            const float* __restrict__ lw1,
                            float* __restrict__ out, int N)
{
    int idx = blockIdx.x * blockDim.x + threadIdx.x;
    int n = idx >> 4, v = idx & 15;
    if (n >= N) return;

    const float* ag = g_agg + (long long)n * 64;
    float ts = 0.f, tv0 = 0.f, tv1 = 0.f, tv2 = 0.f;
#pragma unroll
    for (int u = 0; u < 16; u++) {
        float l0 = __ldg(lw0 + u * 16 + v);
        float l1 = __ldg(lw1 + u * 16 + v);
        ts  += ag[u] * l0;
        tv0 += ag[16 + u * 3 + 0] * l1;
        tv1 += ag[16 + u * 3 + 1] * l1;
        tv2 += ag[16 + u * 3 + 2] * l1;
    }
    const float s = 0.25f;   // 1/sqrt(MUL)
    ts *= s; tv0 *= s; tv1 *= s; tv2 *= s;

    const float eps = 1e-8f;
    float ns = fabsf(ts);
    float gs = ns / ((1.f + expf(-ns)) * (ns + eps));
    float nv = sqrtf(tv0 * tv0 + tv1 * tv1 + tv2 * tv2);
    float gv = nv / ((1.f + expf(-nv)) * (nv + eps));

    const float* nfp = nf + (long long)n * 64;
    float*       op  = out + (long long)n * 64;
    op[v]              = nfp[v]              + ts  * gs;
    op[16 + v * 3 + 0] = nfp[16 + v * 3 + 0] + tv0 * gv;
    op[16 + v * 3 + 1] = nfp[16 + v * 3 + 1] + tv1 * gv;
    op[16 + v * 3 + 2] = nfp[16 + v * 3 + 2] + tv2 * gv;
}

// --------------------------------------------------------------------------
extern "C" void kernel_launch(void* const* d_in, const int* in_sizes, int n_in,
                              void* d_out, int out_size)
{
    const float* nf  = (const float*)d_in[0];   // node_features (N,64)
    const float* esh = (const float*)d_in[1];   // edge_sh (E,4)
    const float* emb = (const float*)d_in[2];   // edge_radial_emb (E,16)
    const float* w1  = (const float*)d_in[3];   // (16,64)
    const float* b1  = (const float*)d_in[4];   // (64)
    const float* w2  = (const float*)d_in[5];   // (64,1024)
    const float* b2  = (const float*)d_in[6];   // (1024)
    const float* lw0 = (const float*)d_in[7];   // (16,16)
    const float* lw1 = (const float*)d_in[8];   // (16,16)
    const int*   eix = (const int*)d_in[9];     // (2,E)

    int N = in_sizes[0] / 64;
    int E = in_sizes[2] / 16;
    float* out = (float*)d_out;

    cudaFuncSetAttribute(edge_kernel,
                         cudaFuncAttributeMaxDynamicSharedMemorySize, SMEM_BYTES);

    int n4 = N * 16;
    int prepN = (n4 > 65536) ? n4 : 65536;
    prep_kernel<<<(prepN + 255) / 256, 256>>>(w2, w1, n4);
    edge_kernel<<<(E + 127) / 128, 256, SMEM_BYTES>>>(nf, esh, emb, b1, b2, eix, E);
    node_kernel<<<(N * 16 + 255) / 256, 256>>>(nf, lw0, lw1, out, N);
}